// round 7
// baseline (speedup 1.0000x reference)
#include <cuda_runtime.h>
#include <cuda_bf16.h>
#include <math.h>

#define NB 64
#define S 256
#define D 1024
#define NH 16
#define NKV 4
#define HD 64
#define NIMG 240
#define MROWS (NB * S)       // 16384
#define KVD (NKV * HD)       // 256
#define NFUSE 1536           // packed QKV output columns

typedef __nv_bfloat16 bf16;

#define ARENA_BYTES 420000000ULL
__device__ __align__(256) char g_arena[ARENA_BYTES];

// ---------------------------------------------------------------------------
// helpers
// ---------------------------------------------------------------------------
__device__ __forceinline__ unsigned smem_u32(const void* p) {
    unsigned a;
    asm("{ .reg .u64 t; cvta.to.shared.u64 t, %1; cvt.u32.u64 %0, t; }" : "=r"(a) : "l"(p));
    return a;
}
__device__ __forceinline__ void cpa16(unsigned saddr, const void* g) {
    asm volatile("cp.async.cg.shared.global [%0], [%1], 16;" :: "r"(saddr), "l"(g));
}
#define CP_COMMIT() asm volatile("cp.async.commit_group;")
#define CP_WAIT1()  asm volatile("cp.async.wait_group 1;")
#define CP_WAIT0()  asm volatile("cp.async.wait_group 0;")

__device__ __forceinline__ unsigned pack_bf16(bf16 a, bf16 b) {
    return (unsigned)__bfloat16_as_ushort(a) | ((unsigned)__bfloat16_as_ushort(b) << 16);
}
__device__ __forceinline__ void split_bf16(float x, bf16& h, bf16& l) {
    h = __float2bfloat16_rn(x);
    l = __float2bfloat16_rn(x - __bfloat162float(h));
}
__device__ __forceinline__ void mma16816(float c[4], const unsigned a[4],
                                         unsigned b0, unsigned b1) {
    asm volatile(
        "mma.sync.aligned.m16n8k16.row.col.f32.bf16.bf16.f32 "
        "{%0,%1,%2,%3}, {%4,%5,%6,%7}, {%8,%9}, {%0,%1,%2,%3};"
        : "+f"(c[0]), "+f"(c[1]), "+f"(c[2]), "+f"(c[3])
        : "r"(a[0]), "r"(a[1]), "r"(a[2]), "r"(a[3]), "r"(b0), "r"(b1));
}
__device__ __forceinline__ void mma_s8(int c[4], const unsigned a[4],
                                       unsigned b0, unsigned b1) {
    asm volatile(
        "mma.sync.aligned.m16n8k32.row.col.s32.s8.s8.s32 "
        "{%0,%1,%2,%3}, {%4,%5,%6,%7}, {%8,%9}, {%0,%1,%2,%3};"
        : "+r"(c[0]), "+r"(c[1]), "+r"(c[2]), "+r"(c[3])
        : "r"(a[0]), "r"(a[1]), "r"(a[2]), "r"(a[3]), "r"(b0), "r"(b1));
}
__device__ __forceinline__ void ldm_x4(unsigned r[4], unsigned addr) {
    asm volatile("ldmatrix.sync.aligned.m8n8.x4.shared.b16 {%0,%1,%2,%3}, [%4];"
                 : "=r"(r[0]), "=r"(r[1]), "=r"(r[2]), "=r"(r[3]) : "r"(addr));
}
__device__ __forceinline__ void ldm_x2(unsigned& r0, unsigned& r1, unsigned addr) {
    asm volatile("ldmatrix.sync.aligned.m8n8.x2.shared.b16 {%0,%1}, [%2];"
                 : "=r"(r0), "=r"(r1) : "r"(addr));
}
__device__ __forceinline__ void ldm_x2t(unsigned& r0, unsigned& r1, unsigned addr) {
    asm volatile("ldmatrix.sync.aligned.m8n8.x2.trans.shared.b16 {%0,%1}, [%2];"
                 : "=r"(r0), "=r"(r1) : "r"(addr));
}

// ---------------------------------------------------------------------------
// Prepass: fp32 transpose W[k][n] -> T[rowOff + n][k]
// ---------------------------------------------------------------------------
__global__ void __launch_bounds__(256)
transp32(const float* __restrict__ W, float* __restrict__ T,
         int Kd, int Nd, int rowOff) {
    __shared__ float t[32][33];
    const int n0 = blockIdx.x * 32, k0 = blockIdx.y * 32;
    const int tx = threadIdx.x, ty = threadIdx.y;   // 32 x 8
    #pragma unroll
    for (int i = 0; i < 4; i++)
        t[ty + 8 * i][tx] = W[(size_t)(k0 + ty + 8 * i) * Nd + n0 + tx];
    __syncthreads();
    #pragma unroll
    for (int i = 0; i < 4; i++)
        T[(size_t)(rowOff + n0 + ty + 8 * i) * Kd + k0 + tx] = t[tx][ty + 8 * i];
}

// ---------------------------------------------------------------------------
// Prepass: per-row 2-slice int8 quantization (rows of 1024 fp32).
// val ~= scale * (q0 + q1/128)
// ---------------------------------------------------------------------------
__global__ void __launch_bounds__(256)
quant_rows(const float* __restrict__ in, char* __restrict__ q0,
           char* __restrict__ q1, float* __restrict__ scale, int rows) {
    int wrow = blockIdx.x * 8 + (threadIdx.x >> 5);
    if (wrow >= rows) return;
    int lane = threadIdx.x & 31;
    const float4* src = (const float4*)(in + (size_t)wrow * 1024);
    float4 v[8];
    float mx = 0.0f;
    #pragma unroll
    for (int j = 0; j < 8; j++) {
        v[j] = src[lane + j * 32];
        mx = fmaxf(mx, fmaxf(fmaxf(fabsf(v[j].x), fabsf(v[j].y)),
                             fmaxf(fabsf(v[j].z), fabsf(v[j].w))));
    }
    #pragma unroll
    for (int o = 16; o; o >>= 1) mx = fmaxf(mx, __shfl_xor_sync(0xffffffffu, mx, o));
    mx = fmaxf(mx, 1e-20f);
    float sa = mx * (1.0f / 127.0f);
    float inv = 127.0f / mx;
    float inv2 = 128.0f / sa;
    if (lane == 0) scale[wrow] = sa;
    char4* d0 = (char4*)(q0 + (size_t)wrow * 1024);
    char4* d1 = (char4*)(q1 + (size_t)wrow * 1024);
    #pragma unroll
    for (int j = 0; j < 8; j++) {
        float xs[4] = {v[j].x, v[j].y, v[j].z, v[j].w};
        int a0[4], a1[4];
        #pragma unroll
        for (int t = 0; t < 4; t++) {
            a0[t] = __float2int_rn(xs[t] * inv);
            float r = xs[t] - (float)a0[t] * sa;
            a1[t] = __float2int_rn(r * inv2);
        }
        d0[lane + j * 32] = make_char4((char)a0[0], (char)a0[1], (char)a0[2], (char)a0[3]);
        d1[lane + j * 32] = make_char4((char)a1[0], (char)a1[1], (char)a1[2], (char)a1[3]);
    }
}

// ---------------------------------------------------------------------------
// int8 2-slice emulated-fp32 GEMM.
// A: [M][K] int8 slices + per-row scale ; B: [N][K] int8 slices + per-row scale.
// out = sA[m]*sB[n]*(P0 + P1/128),  P0 = A0B0,  P1 = A0B1 + A1B0.
// CTA 128x128, BK=64, cp.async double buffer, 8 warps (2x4), warp 64x32.
// mode 0: C fp32 at stride N.
// mode 2: fused QKV routing (cols<1024 -> C fp32 stride D; <1280 -> C2 fp32
//         stride KVD; else -> Ch/Cl bf16 split stride KVD).
// ---------------------------------------------------------------------------
#define GTB (128 * 80)              // tile bytes: 128 rows x 80B pitch (64B data)
#define GEMM_SMEM (2 * 4 * GTB)     // 81920

__global__ void __launch_bounds__(256)
gemm_s8(const char* __restrict__ Aq0, const char* __restrict__ Aq1,
        const float* __restrict__ sA,
        const char* __restrict__ Bq0, const char* __restrict__ Bq1,
        const float* __restrict__ sB,
        float* __restrict__ C, float* __restrict__ C2,
        bf16* __restrict__ Ch, bf16* __restrict__ Cl,
        int M, int N, int K, int mode) {
    extern __shared__ char smg[];
    const unsigned sb = smem_u32(smg);
    const int tid = threadIdx.x;
    const int wid = tid >> 5;
    const int lane = tid & 31;
    const int lr = lane >> 2, lc = lane & 3;

    const int bm = blockIdx.y * 128;
    const int bn = blockIdx.x * 128;
    const int wm = (wid >> 2) * 64;
    const int wn = (wid & 3) * 32;

    // staging: thread covers 32B of one 64B row, two 16B cp.async chunks
    const int srow = tid >> 1, shalf = tid & 1;
    const size_t gaBase = (size_t)(bm + srow) * K + shalf * 32;
    const size_t gbBase = (size_t)(bn + srow) * K + shalf * 32;
    const unsigned soff = srow * 80 + shalf * 32;

    // ldmatrix per-lane byte bases within a tile
    const unsigned aBase = (unsigned)((wm + (lane & 7) + ((lane >> 3) & 1) * 8) * 80
                                      + ((lane >> 4) & 1) * 16);
    const unsigned bBase = (unsigned)((wn + (lane & 7)) * 80 + ((lane >> 3) & 1) * 16);

    int p0[4][4][4] = {};
    int p1[4][4][4] = {};
    const int NCH = K / 64;

    // prologue: stage chunk 0
    {
        unsigned base = sb + soff;
        cpa16(base,                Aq0 + gaBase);
        cpa16(base + 16,           Aq0 + gaBase + 16);
        cpa16(base + GTB,          Aq1 + gaBase);
        cpa16(base + GTB + 16,     Aq1 + gaBase + 16);
        cpa16(base + 2 * GTB,      Bq0 + gbBase);
        cpa16(base + 2 * GTB + 16, Bq0 + gbBase + 16);
        cpa16(base + 3 * GTB,      Bq1 + gbBase);
        cpa16(base + 3 * GTB + 16, Bq1 + gbBase + 16);
        CP_COMMIT();
    }

    for (int ch = 0; ch < NCH; ch++) {
        const int s = ch & 1;
        if (ch + 1 < NCH) {
            unsigned base = sb + (s ^ 1) * 4 * GTB + soff;
            size_t ka = gaBase + (size_t)(ch + 1) * 64;
            size_t kb = gbBase + (size_t)(ch + 1) * 64;
            cpa16(base,                Aq0 + ka);
            cpa16(base + 16,           Aq0 + ka + 16);
            cpa16(base + GTB,          Aq1 + ka);
            cpa16(base + GTB + 16,     Aq1 + ka + 16);
            cpa16(base + 2 * GTB,      Bq0 + kb);
            cpa16(base + 2 * GTB + 16, Bq0 + kb + 16);
            cpa16(base + 3 * GTB,      Bq1 + kb);
            cpa16(base + 3 * GTB + 16, Bq1 + kb + 16);
            CP_COMMIT();
            CP_WAIT1();
        } else {
            CP_WAIT0();
        }
        __syncthreads();

        const unsigned uA0 = sb + s * 4 * GTB;
        const unsigned uA1 = uA0 + GTB;
        const unsigned uB0 = uA0 + 2 * GTB;
        const unsigned uB1 = uA0 + 3 * GTB;

        #pragma unroll
        for (int ks = 0; ks < 2; ks++) {
            const unsigned ko = ks * 32;   // 32 k-bytes per step
            unsigned a0f[4][4], a1f[4][4], b0f[4][2], b1f[4][2];
            #pragma unroll
            for (int mi = 0; mi < 4; mi++) {
                unsigned adr = aBase + mi * 16 * 80 + ko;
                ldm_x4(a0f[mi], uA0 + adr);
                ldm_x4(a1f[mi], uA1 + adr);
            }
            #pragma unroll
            for (int ni = 0; ni < 4; ni++) {
                unsigned adr = bBase + ni * 8 * 80 + ko;
                ldm_x2(b0f[ni][0], b0f[ni][1], uB0 + adr);
                ldm_x2(b1f[ni][0], b1f[ni][1], uB1 + adr);
            }
            #pragma unroll
            for (int mi = 0; mi < 4; mi++)
                #pragma unroll
                for (int ni = 0; ni < 4; ni++)
                    mma_s8(p0[mi][ni], a0f[mi], b0f[ni][0], b0f[ni][1]);
            #pragma unroll
            for (int mi = 0; mi < 4; mi++)
                #pragma unroll
                for (int ni = 0; ni < 4; ni++)
                    mma_s8(p1[mi][ni], a0f[mi], b1f[ni][0], b1f[ni][1]);
            #pragma unroll
            for (int mi = 0; mi < 4; mi++)
                #pragma unroll
                for (int ni = 0; ni < 4; ni++)
                    mma_s8(p1[mi][ni], a1f[mi], b0f[ni][0], b0f[ni][1]);
        }
        __syncthreads();
    }

    // ---- epilogue: combine slices with scales, route by mode ----
    #pragma unroll
    for (int mi = 0; mi < 4; mi++) {
        const int r = bm + wm + mi * 16 + lr;
        const float sa0 = sA[r], sa1 = sA[r + 8];
        #pragma unroll
        for (int ni = 0; ni < 4; ni++) {
            int gcol = bn + wn + ni * 8 + lc * 2;
            const float sb0 = sB[gcol], sb1 = sB[gcol + 1];
            float v00 = sa0 * sb0 * ((float)p0[mi][ni][0] + (float)p1[mi][ni][0] * 0.0078125f);
            float v01 = sa0 * sb1 * ((float)p0[mi][ni][1] + (float)p1[mi][ni][1] * 0.0078125f);
            float v10 = sa1 * sb0 * ((float)p0[mi][ni][2] + (float)p1[mi][ni][2] * 0.0078125f);
            float v11 = sa1 * sb1 * ((float)p0[mi][ni][3] + (float)p1[mi][ni][3] * 0.0078125f);

            if (mode == 0) {
                *(float2*)&C[(size_t)r * N + gcol] = make_float2(v00, v01);
                *(float2*)&C[(size_t)(r + 8) * N + gcol] = make_float2(v10, v11);
            } else if (gcol < 1024) {
                *(float2*)&C[(size_t)r * D + gcol] = make_float2(v00, v01);
                *(float2*)&C[(size_t)(r + 8) * D + gcol] = make_float2(v10, v11);
            } else if (gcol < 1280) {
                int col = gcol - 1024;
                *(float2*)&C2[(size_t)r * KVD + col] = make_float2(v00, v01);
                *(float2*)&C2[(size_t)(r + 8) * KVD + col] = make_float2(v10, v11);
            } else {
                int col = gcol - 1280;
                unsigned* Oh32 = (unsigned*)Ch;
                unsigned* Ol32 = (unsigned*)Cl;
                bf16 h0, l0, h1, l1;
                split_bf16(v00, h0, l0);
                split_bf16(v01, h1, l1);
                Oh32[((size_t)r * KVD + col) >> 1] = pack_bf16(h0, h1);
                Ol32[((size_t)r * KVD + col) >> 1] = pack_bf16(l0, l1);
                split_bf16(v10, h0, l0);
                split_bf16(v11, h1, l1);
                Oh32[((size_t)(r + 8) * KVD + col) >> 1] = pack_bf16(h0, h1);
                Ol32[((size_t)(r + 8) * KVD + col) >> 1] = pack_bf16(l0, l1);
            }
        }
    }
}

// ---------------------------------------------------------------------------
// RMSNorm + RoPE: fp32 Q/K in, bf16 hi/lo out (unchanged)
// ---------------------------------------------------------------------------
__global__ void __launch_bounds__(256)
rmsrope_kernel(const float* __restrict__ Qf, const float* __restrict__ Kf,
               bf16* __restrict__ Qh, bf16* __restrict__ Ql,
               bf16* __restrict__ Kh, bf16* __restrict__ Kl,
               const float* __restrict__ rope_cos, const float* __restrict__ rope_sin,
               const float* __restrict__ q_scale, const float* __restrict__ k_scale) {
    const int w = blockIdx.x * 8 + (threadIdx.x >> 5);
    const int lane = threadIdx.x & 31;

    const float* p;
    bf16 *oh, *ol;
    const float* scale;
    int s_idx;
    size_t base;
    if (w < 262144) {
        int ns = w >> 4;
        int h = w & 15;
        base = (size_t)ns * D + h * HD;
        p = Qf + base; oh = Qh + base; ol = Ql + base;
        scale = q_scale;
        s_idx = ns & 255;
    } else {
        int w2 = w - 262144;
        int ns = w2 >> 2;
        int h = w2 & 3;
        base = (size_t)ns * KVD + h * HD;
        p = Kf + base; oh = Kh + base; ol = Kl + base;
        scale = k_scale;
        s_idx = ns & 255;
    }

    float v1 = p[lane];
    float v2 = p[lane + 32];
    float ss = v1 * v1 + v2 * v2;
    #pragma unroll
    for (int o = 16; o; o >>= 1) ss += __shfl_xor_sync(0xffffffffu, ss, o);
    float r = rsqrtf(ss * (1.0f / 64.0f) + 1e-6f);

    float a = v1 * r * scale[lane];
    float b = v2 * r * scale[lane + 32];
    float cc = rope_cos[s_idx * 32 + lane];
    float sn = rope_sin[s_idx * 32 + lane];
    float r1 = a * cc - b * sn;
    float r2 = b * cc + a * sn;
    bf16 h, l;
    split_bf16(r1, h, l);
    oh[lane] = h; ol[lane] = l;
    split_bf16(r2, h, l);
    oh[lane + 32] = h; ol[lane + 32] = l;
}

// ---------------------------------------------------------------------------
// Flash-attention HMMA kernel; epilogue now writes fp32 O.
// ---------------------------------------------------------------------------
#define KVP 72
#define ATTN_SMEM (4 * 256 * KVP * 2)

__global__ void __launch_bounds__(256, 1)
attn_mma(const bf16* __restrict__ Qh, const bf16* __restrict__ Ql,
         const bf16* __restrict__ Kh, const bf16* __restrict__ Kl,
         const bf16* __restrict__ Vh, const bf16* __restrict__ Vl,
         float* __restrict__ Of) {
    extern __shared__ char sma[];
    bf16* sKh = (bf16*)sma;
    bf16* sKl = sKh + 256 * KVP;
    bf16* sVh = sKl + 256 * KVP;
    bf16* sVl = sVh + 256 * KVP;

    const int bid = blockIdx.x;
    const int n = bid >> 4;
    const int h = bid & 15;
    const int hkv = h >> 2;
    const int tid = threadIdx.x;
    const int w = tid >> 5;
    const int lane = tid & 31;
    const int lr = lane >> 2, lc = lane & 3;

    {
        const bf16* srcs[4] = {Kh, Kl, Vh, Vl};
        bf16* dsts[4] = {sKh, sKl, sVh, sVl};
        #pragma unroll
        for (int a = 0; a < 4; a++) {
            const char* src = (const char*)(srcs[a] + (size_t)n * 256 * KVD + hkv * HD);
            char* dst = (char*)dsts[a];
            for (int it = tid; it < 2048; it += 256) {
                int row = it >> 3, q = it & 7;
                *(uint4*)(dst + row * (KVP * 2) + q * 16) =
                    *(const uint4*)(src + (size_t)row * (KVD * 2) + q * 16);
            }
        }
    }
    __syncthreads();

    const unsigned uKh = smem_u32(sKh), uKl = smem_u32(sKl);
    const unsigned uVh = smem_u32(sVh), uVl = smem_u32(sVl);
    const unsigned* Q32h = (const unsigned*)Qh;
    const unsigned* Q32l = (const unsigned*)Ql;

    const int wq0 = w * 32;
    float o[2][8][4] = {};
    float mrun[2][2] = {{-3e38f, -3e38f}, {-3e38f, -3e38f}};
    float lrun[2][2] = {{0.f, 0.f}, {0.f, 0.f}};

    for (int j = 0; j < 4; j++) {
        float c[2][8][4] = {};

        #pragma unroll
        for (int kt = 0; kt < 4; kt++) {
            unsigned qh[2][4], ql[2][4];
            #pragma unroll
            for (int mt = 0; mt < 2; mt++) {
                size_t row = (size_t)n * 256 + wq0 + mt * 16 + lr;
                size_t b0 = row * 512 + h * 32 + kt * 8 + lc;
                qh[mt][0] = Q32h[b0];
                qh[mt][1] = Q32h[b0 + 8 * 512];
                qh[mt][2] = Q32h[b0 + 4];
                qh[mt][3] = Q32h[b0 + 8 * 512 + 4];
                ql[mt][0] = Q32l[b0];
                ql[mt][1] = Q32l[b0 + 8 * 512];
                ql[mt][2] = Q32l[b0 + 4];
                ql[mt][3] = Q32l[b0 + 8 * 512 + 4];
            }
            #pragma unroll
            for (int nt = 0; nt < 8; nt++) {
                int krow = j * 64 + nt * 8 + (lane & 7);
                int kcol = kt * 16 + ((lane >> 3) & 1) * 8;
                unsigned adr = (unsigned)(krow * KVP + kcol) * 2;
                unsigned kh0, kh1, kl0, kl1;
                ldm_x2(kh0, kh1, uKh + adr);
                ldm_x2(kl0, kl1, uKl + adr);
                #pragma unroll
                for (int mt = 0; mt < 2; mt++) {
                    mma16816(c[mt][nt], qh[mt], kh0, kh1);
                    mma16816(c[mt][nt], qh[mt], kl0, kl1);
                    mma16816(c[mt][nt], ql[mt], kh0, kh1);
                }
            }
        }

        #pragma unroll
        for (int mt = 0; mt < 2; mt++) {
            #pragma unroll
            for (int half = 0; half < 2; half++) {
                const int qr = wq0 + mt * 16 + lr + 8 * half;
                float bmax = -3e38f;
                #pragma unroll
                for (int nt = 0; nt < 8; nt++) {
                    #pragma unroll
                    for (int e = 0; e < 2; e++) {
                        float s = c[mt][nt][2 * half + e] * 0.125f;
                        float t = __expf(s * 0.04f);
                        s = 50.0f * __fdividef(t - 1.0f, t + 1.0f);
                        int col = j * 64 + nt * 8 + 2 * lc + e;
                        if (!((qr >= NIMG) || (col < NIMG))) s = -3e38f;
                        c[mt][nt][2 * half + e] = s;
                        bmax = fmaxf(bmax, s);
                    }
                }
                bmax = fmaxf(bmax, __shfl_xor_sync(0xffffffffu, bmax, 1));
                bmax = fmaxf(bmax, __shfl_xor_sync(0xffffffffu, bmax, 2));
                float mold = mrun[mt][half];
                float mnew = fmaxf(mold, bmax);
                float resc = __expf(mold - mnew);
                float rs = 0.0f;
                #pragma unroll
                for (int nt = 0; nt < 8; nt++) {
                    #pragma unroll
                    for (int e = 0; e < 2; e++) {
                        float p = __expf(c[mt][nt][2 * half + e] - mnew);
                        c[mt][nt][2 * half + e] = p;
                        rs += p;
                    }
                }
                rs += __shfl_xor_sync(0xffffffffu, rs, 1);
                rs += __shfl_xor_sync(0xffffffffu, rs, 2);
                lrun[mt][half] = lrun[mt][half] * resc + rs;
                mrun[mt][half] = mnew;
                #pragma unroll
                for (int dt = 0; dt < 8; dt++) {
                    o[mt][dt][2 * half]     *= resc;
                    o[mt][dt][2 * half + 1] *= resc;
                }
            }
        }

        #pragma unroll
        for (int kt = 0; kt < 4; kt++) {
            unsigned ph[2][4], pl[2][4];
            #pragma unroll
            for (int mt = 0; mt < 2; mt++) {
                bf16 h0, l0, h1, l1;
                split_bf16(c[mt][2 * kt][0], h0, l0);
                split_bf16(c[mt][2 * kt][1], h1, l1);
                ph[mt][0] = pack_bf16(h0, h1); pl[mt][0] = pack_bf16(l0, l1);
                split_bf16(c[mt][2 * kt][2], h0, l0);
                split_bf16(c[mt][2 * kt][3], h1, l1);
                ph[mt][1] = pack_bf16(h0, h1); pl[mt][1] = pack_bf16(l0, l1);
                split_bf16(c[mt][2 * kt + 1][0], h0, l0);
                split_bf16(c[mt][2 * kt + 1][1], h1, l1);
                ph[mt][2] = pack_bf16(h0, h1); pl[mt][2] = pack_bf16(l0, l1);
                split_bf16(c[mt][2 * kt + 1][2], h0, l0);
                split_bf16(c[mt][2 * kt + 1][3], h1, l1);
                ph[mt][3] = pack_bf16(h0, h1); pl[mt][3] = pack_bf16(l0, l1);
            }
            #pragma unroll
            for (int dt = 0; dt < 8; dt++) {
                int vrow = j * 64 + kt * 16 + (lane & 15);
                unsigned adr = (unsigned)(vrow * KVP + dt * 8) * 2;
                unsigned vh0, vh1, vl0, vl1;
                ldm_x2t(vh0, vh1, uVh + adr);
                ldm_x2t(vl0, vl1, uVl + adr);
                #pragma unroll
                for (int mt = 0; mt < 2; mt++) {
                    mma16816(o[mt][dt], ph[mt], vh0, vh1);
                    mma16816(o[mt][dt], ph[mt], vl0, vl1);
                    mma16816(o[mt][dt], pl[mt], vh0, vh1);
                }
            }
        }
    }

    // epilogue: normalize + fp32 store
    #pragma unroll
    for (int mt = 0; mt < 2; mt++) {
        float inv0 = __fdividef(1.0f, lrun[mt][0]);
        float inv1 = __fdividef(1.0f, lrun[mt][1]);
        size_t r0 = (size_t)n * 256 + wq0 + mt * 16 + lr;
        #pragma unroll
        for (int dt = 0; dt < 8; dt++) {
            size_t i0 = r0 * 1024 + h * 64 + dt * 8 + lc * 2;
            *(float2*)&Of[i0] = make_float2(o[mt][dt][0] * inv0, o[mt][dt][1] * inv0);
            size_t i1 = (r0 + 8) * 1024 + h * 64 + dt * 8 + lc * 2;
            *(float2*)&Of[i1] = make_float2(o[mt][dt][2] * inv1, o[mt][dt][3] * inv1);
        }
    }
}

// ---------------------------------------------------------------------------
extern "C" void kernel_launch(void* const* d_in, const int* in_sizes, int n_in,
                              void* d_out, int out_size) {
    const float* x        = (const float*)d_in[0];
    const float* rope_cos = (const float*)d_in[2];
    const float* rope_sin = (const float*)d_in[3];
    const float* Wq       = (const float*)d_in[4];
    const float* Wk       = (const float*)d_in[5];
    const float* Wv       = (const float*)d_in[6];
    const float* Wo       = (const float*)d_in[7];
    const float* q_scale  = (const float*)d_in[8];
    const float* k_scale  = (const float*)d_in[9];
    float* out = (float*)d_out;

    char* base;
    cudaGetSymbolAddress((void**)&base, g_arena);
    size_t cur = 0;
    auto alloc = [&](size_t bytes) { char* p = base + cur; cur += (bytes + 255) & ~255ULL; return p; };

    float* Qf  = (float*)alloc((size_t)MROWS * D * 4);
    float* Kf  = (float*)alloc((size_t)MROWS * KVD * 4);
    float* Of  = (float*)alloc((size_t)MROWS * D * 4);
    bf16* Qhh  = (bf16*)alloc((size_t)MROWS * D * 2);
    bf16* Qll  = (bf16*)alloc((size_t)MROWS * D * 2);
    bf16* Khh  = (bf16*)alloc((size_t)MROWS * KVD * 2);
    bf16* Kll  = (bf16*)alloc((size_t)MROWS * KVD * 2);
    bf16* Vhh  = (bf16*)alloc((size_t)MROWS * KVD * 2);
    bf16* Vll  = (bf16*)alloc((size_t)MROWS * KVD * 2);
    char* xq0  = alloc((size_t)MROWS * D);
    char* xq1  = alloc((size_t)MROWS * D);
    char* Oq0  = alloc((size_t)MROWS * D);
    char* Oq1  = alloc((size_t)MROWS * D);
    float* WTp = (float*)alloc((size_t)NFUSE * D * 4);   // packed QKV W^T fp32
    float* WoT = (float*)alloc((size_t)D * D * 4);
    char* Wp0  = alloc((size_t)NFUSE * D);
    char* Wp1  = alloc((size_t)NFUSE * D);
    char* Wo0  = alloc((size_t)D * D);
    char* Wo1  = alloc((size_t)D * D);
    float* sx  = (float*)alloc((size_t)MROWS * 4);
    float* sO  = (float*)alloc((size_t)MROWS * 4);
    float* sWp = (float*)alloc((size_t)NFUSE * 4);
    float* sWo = (float*)alloc((size_t)D * 4);

    cudaFuncSetAttribute(gemm_s8, cudaFuncAttributeMaxDynamicSharedMemorySize, GEMM_SMEM);
    cudaFuncSetAttribute(attn_mma, cudaFuncAttributeMaxDynamicSharedMemorySize, ATTN_SMEM);

    dim3 thr(256);
    // weight prepasses
    transp32<<<dim3(D / 32, D / 32), dim3(32, 8)>>>(Wq, WTp, D, D, 0);
    transp32<<<dim3(KVD / 32, D / 32), dim3(32, 8)>>>(Wk, WTp, D, KVD, 1024);
    transp32<<<dim3(KVD / 32, D / 32), dim3(32, 8)>>>(Wv, WTp, D, KVD, 1280);
    transp32<<<dim3(D / 32, D / 32), dim3(32, 8)>>>(Wo, WoT, D, D, 0);
    quant_rows<<<NFUSE / 8, thr>>>(WTp, Wp0, Wp1, sWp, NFUSE);
    quant_rows<<<D / 8, thr>>>(WoT, Wo0, Wo1, sWo, D);
    // activation quantization
    quant_rows<<<MROWS / 8, thr>>>(x, xq0, xq1, sx, MROWS);

    // fused QKV projection (int8 2-slice)
    gemm_s8<<<dim3(NFUSE / 128, MROWS / 128), thr, GEMM_SMEM>>>(
        xq0, xq1, sx, Wp0, Wp1, sWp, Qf, Kf, Vhh, Vll, MROWS, NFUSE, D, 2);

    // rmsnorm + rope -> bf16 splits
    rmsrope_kernel<<<(262144 + 65536) / 8, thr>>>(
        Qf, Kf, Qhh, Qll, Khh, Kll, rope_cos, rope_sin, q_scale, k_scale);

    // attention (bf16x3 HMMA) -> fp32 O
    attn_mma<<<NB * NH, thr, ATTN_SMEM>>>(Qhh, Qll, Khh, Kll, Vhh, Vll, Of);

    // quantize O, output projection
    quant_rows<<<MROWS / 8, thr>>>(Of, Oq0, Oq1, sO, MROWS);
    gemm_s8<<<dim3(D / 128, MROWS / 128), thr, GEMM_SMEM>>>(
        Oq0, Oq1, sO, Wo0, Wo1, sWo, out, nullptr, nullptr, nullptr, MROWS, D, D, 0);
}

// round 8
// speedup vs baseline: 1.0018x; 1.0018x over previous
#include <cuda_runtime.h>
#include <cuda_bf16.h>
#include <math.h>

#define NB 64
#define S 256
#define D 1024
#define NH 16
#define NKV 4
#define HD 64
#define NIMG 240
#define MROWS (NB * S)       // 16384
#define KVD (NKV * HD)       // 256
#define NFUSE 1536           // packed QKV output columns

typedef __nv_bfloat16 bf16;

#define ARENA_BYTES 420000000ULL
__device__ __align__(256) char g_arena[ARENA_BYTES];

// ---------------------------------------------------------------------------
// helpers
// ---------------------------------------------------------------------------
__device__ __forceinline__ unsigned smem_u32(const void* p) {
    unsigned a;
    asm("{ .reg .u64 t; cvta.to.shared.u64 t, %1; cvt.u32.u64 %0, t; }" : "=r"(a) : "l"(p));
    return a;
}
__device__ __forceinline__ void cpa16(unsigned saddr, const void* g) {
    asm volatile("cp.async.cg.shared.global [%0], [%1], 16;" :: "r"(saddr), "l"(g));
}
#define CP_COMMIT() asm volatile("cp.async.commit_group;")
#define CP_WAIT1()  asm volatile("cp.async.wait_group 1;")
#define CP_WAIT0()  asm volatile("cp.async.wait_group 0;")

__device__ __forceinline__ unsigned pack_bf16(bf16 a, bf16 b) {
    return (unsigned)__bfloat16_as_ushort(a) | ((unsigned)__bfloat16_as_ushort(b) << 16);
}
__device__ __forceinline__ void split_bf16(float x, bf16& h, bf16& l) {
    h = __float2bfloat16_rn(x);
    l = __float2bfloat16_rn(x - __bfloat162float(h));
}
__device__ __forceinline__ void mma16816(float c[4], const unsigned a[4],
                                         unsigned b0, unsigned b1) {
    asm volatile(
        "mma.sync.aligned.m16n8k16.row.col.f32.bf16.bf16.f32 "
        "{%0,%1,%2,%3}, {%4,%5,%6,%7}, {%8,%9}, {%0,%1,%2,%3};"
        : "+f"(c[0]), "+f"(c[1]), "+f"(c[2]), "+f"(c[3])
        : "r"(a[0]), "r"(a[1]), "r"(a[2]), "r"(a[3]), "r"(b0), "r"(b1));
}
__device__ __forceinline__ void mma_s8(int c[4], const unsigned a[4],
                                       unsigned b0, unsigned b1) {
    asm volatile(
        "mma.sync.aligned.m16n8k32.row.col.s32.s8.s8.s32 "
        "{%0,%1,%2,%3}, {%4,%5,%6,%7}, {%8,%9}, {%0,%1,%2,%3};"
        : "+r"(c[0]), "+r"(c[1]), "+r"(c[2]), "+r"(c[3])
        : "r"(a[0]), "r"(a[1]), "r"(a[2]), "r"(a[3]), "r"(b0), "r"(b1));
}
__device__ __forceinline__ void ldm_x4(unsigned r[4], unsigned addr) {
    asm volatile("ldmatrix.sync.aligned.m8n8.x4.shared.b16 {%0,%1,%2,%3}, [%4];"
                 : "=r"(r[0]), "=r"(r[1]), "=r"(r[2]), "=r"(r[3]) : "r"(addr));
}
__device__ __forceinline__ void ldm_x2(unsigned& r0, unsigned& r1, unsigned addr) {
    asm volatile("ldmatrix.sync.aligned.m8n8.x2.shared.b16 {%0,%1}, [%2];"
                 : "=r"(r0), "=r"(r1) : "r"(addr));
}
__device__ __forceinline__ void ldm_x2t(unsigned& r0, unsigned& r1, unsigned addr) {
    asm volatile("ldmatrix.sync.aligned.m8n8.x2.trans.shared.b16 {%0,%1}, [%2];"
                 : "=r"(r0), "=r"(r1) : "r"(addr));
}

// ---------------------------------------------------------------------------
// Prepass: fp32 transpose W[k][n] -> T[rowOff + n][k]
// ---------------------------------------------------------------------------
__global__ void __launch_bounds__(256)
transp32(const float* __restrict__ W, float* __restrict__ T,
         int Kd, int Nd, int rowOff) {
    __shared__ float t[32][33];
    const int n0 = blockIdx.x * 32, k0 = blockIdx.y * 32;
    const int tx = threadIdx.x, ty = threadIdx.y;   // 32 x 8
    #pragma unroll
    for (int i = 0; i < 4; i++)
        t[ty + 8 * i][tx] = W[(size_t)(k0 + ty + 8 * i) * Nd + n0 + tx];
    __syncthreads();
    #pragma unroll
    for (int i = 0; i < 4; i++)
        T[(size_t)(rowOff + n0 + ty + 8 * i) * Kd + k0 + tx] = t[tx][ty + 8 * i];
}

// ---------------------------------------------------------------------------
// Prepass: per-row 2-slice int8 quantization (rows of 1024 fp32).
// val ~= scale * (q0 + q1/128)
// ---------------------------------------------------------------------------
__global__ void __launch_bounds__(256)
quant_rows(const float* __restrict__ in, char* __restrict__ q0,
           char* __restrict__ q1, float* __restrict__ scale, int rows) {
    int wrow = blockIdx.x * 8 + (threadIdx.x >> 5);
    if (wrow >= rows) return;
    int lane = threadIdx.x & 31;
    const float4* src = (const float4*)(in + (size_t)wrow * 1024);
    float4 v[8];
    float mx = 0.0f;
    #pragma unroll
    for (int j = 0; j < 8; j++) {
        v[j] = src[lane + j * 32];
        mx = fmaxf(mx, fmaxf(fmaxf(fabsf(v[j].x), fabsf(v[j].y)),
                             fmaxf(fabsf(v[j].z), fabsf(v[j].w))));
    }
    #pragma unroll
    for (int o = 16; o; o >>= 1) mx = fmaxf(mx, __shfl_xor_sync(0xffffffffu, mx, o));
    mx = fmaxf(mx, 1e-20f);
    float sa = mx * (1.0f / 127.0f);
    float inv = 127.0f / mx;
    float inv2 = 128.0f / sa;
    if (lane == 0) scale[wrow] = sa;
    char4* d0 = (char4*)(q0 + (size_t)wrow * 1024);
    char4* d1 = (char4*)(q1 + (size_t)wrow * 1024);
    #pragma unroll
    for (int j = 0; j < 8; j++) {
        float xs[4] = {v[j].x, v[j].y, v[j].z, v[j].w};
        int a0[4], a1[4];
        #pragma unroll
        for (int t = 0; t < 4; t++) {
            a0[t] = __float2int_rn(xs[t] * inv);
            float r = xs[t] - (float)a0[t] * sa;
            a1[t] = __float2int_rn(r * inv2);
        }
        d0[lane + j * 32] = make_char4((char)a0[0], (char)a0[1], (char)a0[2], (char)a0[3]);
        d1[lane + j * 32] = make_char4((char)a1[0], (char)a1[1], (char)a1[2], (char)a1[3]);
    }
}

// ---------------------------------------------------------------------------
// int8 2-slice emulated-fp32 GEMM.
// A: [M][K] int8 slices + per-row scale ; B: [N][K] int8 slices + per-row scale.
// out = sA[m]*sB[n]*(P0 + P1/128),  P0 = A0B0,  P1 = A0B1 + A1B0.
// CTA 128x128, BK=64, cp.async double buffer, 8 warps (2x4), warp 64x32.
// mode 0: C fp32 at stride N.
// mode 2: fused QKV routing (cols<1024 -> C fp32 stride D; <1280 -> C2 fp32
//         stride KVD; else -> Ch/Cl bf16 split stride KVD).
// ---------------------------------------------------------------------------
#define GTB (128 * 80)              // tile bytes: 128 rows x 80B pitch (64B data)
#define GEMM_SMEM (2 * 4 * GTB)     // 81920

__global__ void __launch_bounds__(256)
gemm_s8(const char* __restrict__ Aq0, const char* __restrict__ Aq1,
        const float* __restrict__ sA,
        const char* __restrict__ Bq0, const char* __restrict__ Bq1,
        const float* __restrict__ sB,
        float* __restrict__ C, float* __restrict__ C2,
        bf16* __restrict__ Ch, bf16* __restrict__ Cl,
        int M, int N, int K, int mode) {
    extern __shared__ char smg[];
    const unsigned sb = smem_u32(smg);
    const int tid = threadIdx.x;
    const int wid = tid >> 5;
    const int lane = tid & 31;
    const int lr = lane >> 2, lc = lane & 3;

    const int bm = blockIdx.y * 128;
    const int bn = blockIdx.x * 128;
    const int wm = (wid >> 2) * 64;
    const int wn = (wid & 3) * 32;

    // staging: thread covers 32B of one 64B row, two 16B cp.async chunks
    const int srow = tid >> 1, shalf = tid & 1;
    const size_t gaBase = (size_t)(bm + srow) * K + shalf * 32;
    const size_t gbBase = (size_t)(bn + srow) * K + shalf * 32;
    const unsigned soff = srow * 80 + shalf * 32;

    // ldmatrix per-lane byte bases within a tile
    const unsigned aBase = (unsigned)((wm + (lane & 7) + ((lane >> 3) & 1) * 8) * 80
                                      + ((lane >> 4) & 1) * 16);
    const unsigned bBase = (unsigned)((wn + (lane & 7)) * 80 + ((lane >> 3) & 1) * 16);

    int p0[4][4][4] = {};
    int p1[4][4][4] = {};
    const int NCH = K / 64;

    // prologue: stage chunk 0
    {
        unsigned base = sb + soff;
        cpa16(base,                Aq0 + gaBase);
        cpa16(base + 16,           Aq0 + gaBase + 16);
        cpa16(base + GTB,          Aq1 + gaBase);
        cpa16(base + GTB + 16,     Aq1 + gaBase + 16);
        cpa16(base + 2 * GTB,      Bq0 + gbBase);
        cpa16(base + 2 * GTB + 16, Bq0 + gbBase + 16);
        cpa16(base + 3 * GTB,      Bq1 + gbBase);
        cpa16(base + 3 * GTB + 16, Bq1 + gbBase + 16);
        CP_COMMIT();
    }

    for (int ch = 0; ch < NCH; ch++) {
        const int s = ch & 1;
        if (ch + 1 < NCH) {
            unsigned base = sb + (s ^ 1) * 4 * GTB + soff;
            size_t ka = gaBase + (size_t)(ch + 1) * 64;
            size_t kb = gbBase + (size_t)(ch + 1) * 64;
            cpa16(base,                Aq0 + ka);
            cpa16(base + 16,           Aq0 + ka + 16);
            cpa16(base + GTB,          Aq1 + ka);
            cpa16(base + GTB + 16,     Aq1 + ka + 16);
            cpa16(base + 2 * GTB,      Bq0 + kb);
            cpa16(base + 2 * GTB + 16, Bq0 + kb + 16);
            cpa16(base + 3 * GTB,      Bq1 + kb);
            cpa16(base + 3 * GTB + 16, Bq1 + kb + 16);
            CP_COMMIT();
            CP_WAIT1();
        } else {
            CP_WAIT0();
        }
        __syncthreads();

        const unsigned uA0 = sb + s * 4 * GTB;
        const unsigned uA1 = uA0 + GTB;
        const unsigned uB0 = uA0 + 2 * GTB;
        const unsigned uB1 = uA0 + 3 * GTB;

        #pragma unroll
        for (int ks = 0; ks < 2; ks++) {
            const unsigned ko = ks * 32;   // 32 k-bytes per step
            unsigned a0f[4][4], a1f[4][4], b0f[4][2], b1f[4][2];
            #pragma unroll
            for (int mi = 0; mi < 4; mi++) {
                unsigned adr = aBase + mi * 16 * 80 + ko;
                ldm_x4(a0f[mi], uA0 + adr);
                ldm_x4(a1f[mi], uA1 + adr);
            }
            #pragma unroll
            for (int ni = 0; ni < 4; ni++) {
                unsigned adr = bBase + ni * 8 * 80 + ko;
                ldm_x2(b0f[ni][0], b0f[ni][1], uB0 + adr);
                ldm_x2(b1f[ni][0], b1f[ni][1], uB1 + adr);
            }
            #pragma unroll
            for (int mi = 0; mi < 4; mi++)
                #pragma unroll
                for (int ni = 0; ni < 4; ni++)
                    mma_s8(p0[mi][ni], a0f[mi], b0f[ni][0], b0f[ni][1]);
            #pragma unroll
            for (int mi = 0; mi < 4; mi++)
                #pragma unroll
                for (int ni = 0; ni < 4; ni++)
                    mma_s8(p1[mi][ni], a0f[mi], b1f[ni][0], b1f[ni][1]);
            #pragma unroll
            for (int mi = 0; mi < 4; mi++)
                #pragma unroll
                for (int ni = 0; ni < 4; ni++)
                    mma_s8(p1[mi][ni], a1f[mi], b0f[ni][0], b0f[ni][1]);
        }
        __syncthreads();
    }

    // ---- epilogue: combine slices with scales, route by mode ----
    #pragma unroll
    for (int mi = 0; mi < 4; mi++) {
        const int r = bm + wm + mi * 16 + lr;
        const float sa0 = sA[r], sa1 = sA[r + 8];
        #pragma unroll
        for (int ni = 0; ni < 4; ni++) {
            int gcol = bn + wn + ni * 8 + lc * 2;
            const float sb0 = sB[gcol], sb1 = sB[gcol + 1];
            float v00 = sa0 * sb0 * ((float)p0[mi][ni][0] + (float)p1[mi][ni][0] * 0.0078125f);
            float v01 = sa0 * sb1 * ((float)p0[mi][ni][1] + (float)p1[mi][ni][1] * 0.0078125f);
            float v10 = sa1 * sb0 * ((float)p0[mi][ni][2] + (float)p1[mi][ni][2] * 0.0078125f);
            float v11 = sa1 * sb1 * ((float)p0[mi][ni][3] + (float)p1[mi][ni][3] * 0.0078125f);

            if (mode == 0) {
                *(float2*)&C[(size_t)r * N + gcol] = make_float2(v00, v01);
                *(float2*)&C[(size_t)(r + 8) * N + gcol] = make_float2(v10, v11);
            } else if (gcol < 1024) {
                *(float2*)&C[(size_t)r * D + gcol] = make_float2(v00, v01);
                *(float2*)&C[(size_t)(r + 8) * D + gcol] = make_float2(v10, v11);
            } else if (gcol < 1280) {
                int col = gcol - 1024;
                *(float2*)&C2[(size_t)r * KVD + col] = make_float2(v00, v01);
                *(float2*)&C2[(size_t)(r + 8) * KVD + col] = make_float2(v10, v11);
            } else {
                int col = gcol - 1280;
                unsigned* Oh32 = (unsigned*)Ch;
                unsigned* Ol32 = (unsigned*)Cl;
                bf16 h0, l0, h1, l1;
                split_bf16(v00, h0, l0);
                split_bf16(v01, h1, l1);
                Oh32[((size_t)r * KVD + col) >> 1] = pack_bf16(h0, h1);
                Ol32[((size_t)r * KVD + col) >> 1] = pack_bf16(l0, l1);
                split_bf16(v10, h0, l0);
                split_bf16(v11, h1, l1);
                Oh32[((size_t)(r + 8) * KVD + col) >> 1] = pack_bf16(h0, h1);
                Ol32[((size_t)(r + 8) * KVD + col) >> 1] = pack_bf16(l0, l1);
            }
        }
    }
}

// ---------------------------------------------------------------------------
// RMSNorm + RoPE: fp32 Q/K in, bf16 hi/lo out (unchanged)
// ---------------------------------------------------------------------------
__global__ void __launch_bounds__(256)
rmsrope_kernel(const float* __restrict__ Qf, const float* __restrict__ Kf,
               bf16* __restrict__ Qh, bf16* __restrict__ Ql,
               bf16* __restrict__ Kh, bf16* __restrict__ Kl,
               const float* __restrict__ rope_cos, const float* __restrict__ rope_sin,
               const float* __restrict__ q_scale, const float* __restrict__ k_scale) {
    const int w = blockIdx.x * 8 + (threadIdx.x >> 5);
    const int lane = threadIdx.x & 31;

    const float* p;
    bf16 *oh, *ol;
    const float* scale;
    int s_idx;
    size_t base;
    if (w < 262144) {
        int ns = w >> 4;
        int h = w & 15;
        base = (size_t)ns * D + h * HD;
        p = Qf + base; oh = Qh + base; ol = Ql + base;
        scale = q_scale;
        s_idx = ns & 255;
    } else {
        int w2 = w - 262144;
        int ns = w2 >> 2;
        int h = w2 & 3;
        base = (size_t)ns * KVD + h * HD;
        p = Kf + base; oh = Kh + base; ol = Kl + base;
        scale = k_scale;
        s_idx = ns & 255;
    }

    float v1 = p[lane];
    float v2 = p[lane + 32];
    float ss = v1 * v1 + v2 * v2;
    #pragma unroll
    for (int o = 16; o; o >>= 1) ss += __shfl_xor_sync(0xffffffffu, ss, o);
    float r = rsqrtf(ss * (1.0f / 64.0f) + 1e-6f);

    float a = v1 * r * scale[lane];
    float b = v2 * r * scale[lane + 32];
    float cc = rope_cos[s_idx * 32 + lane];
    float sn = rope_sin[s_idx * 32 + lane];
    float r1 = a * cc - b * sn;
    float r2 = b * cc + a * sn;
    bf16 h, l;
    split_bf16(r1, h, l);
    oh[lane] = h; ol[lane] = l;
    split_bf16(r2, h, l);
    oh[lane + 32] = h; ol[lane + 32] = l;
}

// ---------------------------------------------------------------------------
// Flash-attention HMMA kernel; epilogue now writes fp32 O.
// ---------------------------------------------------------------------------
#define KVP 72
#define ATTN_SMEM (4 * 256 * KVP * 2)

__global__ void __launch_bounds__(256, 1)
attn_mma(const bf16* __restrict__ Qh, const bf16* __restrict__ Ql,
         const bf16* __restrict__ Kh, const bf16* __restrict__ Kl,
         const bf16* __restrict__ Vh, const bf16* __restrict__ Vl,
         float* __restrict__ Of) {
    extern __shared__ char sma[];
    bf16* sKh = (bf16*)sma;
    bf16* sKl = sKh + 256 * KVP;
    bf16* sVh = sKl + 256 * KVP;
    bf16* sVl = sVh + 256 * KVP;

    const int bid = blockIdx.x;
    const int n = bid >> 4;
    const int h = bid & 15;
    const int hkv = h >> 2;
    const int tid = threadIdx.x;
    const int w = tid >> 5;
    const int lane = tid & 31;
    const int lr = lane >> 2, lc = lane & 3;

    {
        const bf16* srcs[4] = {Kh, Kl, Vh, Vl};
        bf16* dsts[4] = {sKh, sKl, sVh, sVl};
        #pragma unroll
        for (int a = 0; a < 4; a++) {
            const char* src = (const char*)(srcs[a] + (size_t)n * 256 * KVD + hkv * HD);
            char* dst = (char*)dsts[a];
            for (int it = tid; it < 2048; it += 256) {
                int row = it >> 3, q = it & 7;
                *(uint4*)(dst + row * (KVP * 2) + q * 16) =
                    *(const uint4*)(src + (size_t)row * (KVD * 2) + q * 16);
            }
        }
    }
    __syncthreads();

    const unsigned uKh = smem_u32(sKh), uKl = smem_u32(sKl);
    const unsigned uVh = smem_u32(sVh), uVl = smem_u32(sVl);
    const unsigned* Q32h = (const unsigned*)Qh;
    const unsigned* Q32l = (const unsigned*)Ql;

    const int wq0 = w * 32;
    float o[2][8][4] = {};
    float mrun[2][2] = {{-3e38f, -3e38f}, {-3e38f, -3e38f}};
    float lrun[2][2] = {{0.f, 0.f}, {0.f, 0.f}};

    for (int j = 0; j < 4; j++) {
        float c[2][8][4] = {};

        #pragma unroll
        for (int kt = 0; kt < 4; kt++) {
            unsigned qh[2][4], ql[2][4];
            #pragma unroll
            for (int mt = 0; mt < 2; mt++) {
                size_t row = (size_t)n * 256 + wq0 + mt * 16 + lr;
                size_t b0 = row * 512 + h * 32 + kt * 8 + lc;
                qh[mt][0] = Q32h[b0];
                qh[mt][1] = Q32h[b0 + 8 * 512];
                qh[mt][2] = Q32h[b0 + 4];
                qh[mt][3] = Q32h[b0 + 8 * 512 + 4];
                ql[mt][0] = Q32l[b0];
                ql[mt][1] = Q32l[b0 + 8 * 512];
                ql[mt][2] = Q32l[b0 + 4];
                ql[mt][3] = Q32l[b0 + 8 * 512 + 4];
            }
            #pragma unroll
            for (int nt = 0; nt < 8; nt++) {
                int krow = j * 64 + nt * 8 + (lane & 7);
                int kcol = kt * 16 + ((lane >> 3) & 1) * 8;
                unsigned adr = (unsigned)(krow * KVP + kcol) * 2;
                unsigned kh0, kh1, kl0, kl1;
                ldm_x2(kh0, kh1, uKh + adr);
                ldm_x2(kl0, kl1, uKl + adr);
                #pragma unroll
                for (int mt = 0; mt < 2; mt++) {
                    mma16816(c[mt][nt], qh[mt], kh0, kh1);
                    mma16816(c[mt][nt], qh[mt], kl0, kl1);
                    mma16816(c[mt][nt], ql[mt], kh0, kh1);
                }
            }
        }

        #pragma unroll
        for (int mt = 0; mt < 2; mt++) {
            #pragma unroll
            for (int half = 0; half < 2; half++) {
                const int qr = wq0 + mt * 16 + lr + 8 * half;
                float bmax = -3e38f;
                #pragma unroll
                for (int nt = 0; nt < 8; nt++) {
                    #pragma unroll
                    for (int e = 0; e < 2; e++) {
                        float s = c[mt][nt][2 * half + e] * 0.125f;
                        float t = __expf(s * 0.04f);
                        s = 50.0f * __fdividef(t - 1.0f, t + 1.0f);
                        int col = j * 64 + nt * 8 + 2 * lc + e;
                        if (!((qr >= NIMG) || (col < NIMG))) s = -3e38f;
                        c[mt][nt][2 * half + e] = s;
                        bmax = fmaxf(bmax, s);
                    }
                }
                bmax = fmaxf(bmax, __shfl_xor_sync(0xffffffffu, bmax, 1));
                bmax = fmaxf(bmax, __shfl_xor_sync(0xffffffffu, bmax, 2));
                float mold = mrun[mt][half];
                float mnew = fmaxf(mold, bmax);
                float resc = __expf(mold - mnew);
                float rs = 0.0f;
                #pragma unroll
                for (int nt = 0; nt < 8; nt++) {
                    #pragma unroll
                    for (int e = 0; e < 2; e++) {
                        float p = __expf(c[mt][nt][2 * half + e] - mnew);
                        c[mt][nt][2 * half + e] = p;
                        rs += p;
                    }
                }
                rs += __shfl_xor_sync(0xffffffffu, rs, 1);
                rs += __shfl_xor_sync(0xffffffffu, rs, 2);
                lrun[mt][half] = lrun[mt][half] * resc + rs;
                mrun[mt][half] = mnew;
                #pragma unroll
                for (int dt = 0; dt < 8; dt++) {
                    o[mt][dt][2 * half]     *= resc;
                    o[mt][dt][2 * half + 1] *= resc;
                }
            }
        }

        #pragma unroll
        for (int kt = 0; kt < 4; kt++) {
            unsigned ph[2][4], pl[2][4];
            #pragma unroll
            for (int mt = 0; mt < 2; mt++) {
                bf16 h0, l0, h1, l1;
                split_bf16(c[mt][2 * kt][0], h0, l0);
                split_bf16(c[mt][2 * kt][1], h1, l1);
                ph[mt][0] = pack_bf16(h0, h1); pl[mt][0] = pack_bf16(l0, l1);
                split_bf16(c[mt][2 * kt][2], h0, l0);
                split_bf16(c[mt][2 * kt][3], h1, l1);
                ph[mt][1] = pack_bf16(h0, h1); pl[mt][1] = pack_bf16(l0, l1);
                split_bf16(c[mt][2 * kt + 1][0], h0, l0);
                split_bf16(c[mt][2 * kt + 1][1], h1, l1);
                ph[mt][2] = pack_bf16(h0, h1); pl[mt][2] = pack_bf16(l0, l1);
                split_bf16(c[mt][2 * kt + 1][2], h0, l0);
                split_bf16(c[mt][2 * kt + 1][3], h1, l1);
                ph[mt][3] = pack_bf16(h0, h1); pl[mt][3] = pack_bf16(l0, l1);
            }
            #pragma unroll
            for (int dt = 0; dt < 8; dt++) {
                int vrow = j * 64 + kt * 16 + (lane & 15);
                unsigned adr = (unsigned)(vrow * KVP + dt * 8) * 2;
                unsigned vh0, vh1, vl0, vl1;
                ldm_x2t(vh0, vh1, uVh + adr);
                ldm_x2t(vl0, vl1, uVl + adr);
                #pragma unroll
                for (int mt = 0; mt < 2; mt++) {
                    mma16816(o[mt][dt], ph[mt], vh0, vh1);
                    mma16816(o[mt][dt], ph[mt], vl0, vl1);
                    mma16816(o[mt][dt], pl[mt], vh0, vh1);
                }
            }
        }
    }

    // epilogue: normalize + fp32 store
    #pragma unroll
    for (int mt = 0; mt < 2; mt++) {
        float inv0 = __fdividef(1.0f, lrun[mt][0]);
        float inv1 = __fdividef(1.0f, lrun[mt][1]);
        size_t r0 = (size_t)n * 256 + wq0 + mt * 16 + lr;
        #pragma unroll
        for (int dt = 0; dt < 8; dt++) {
            size_t i0 = r0 * 1024 + h * 64 + dt * 8 + lc * 2;
            *(float2*)&Of[i0] = make_float2(o[mt][dt][0] * inv0, o[mt][dt][1] * inv0);
            size_t i1 = (r0 + 8) * 1024 + h * 64 + dt * 8 + lc * 2;
            *(float2*)&Of[i1] = make_float2(o[mt][dt][2] * inv1, o[mt][dt][3] * inv1);
        }
    }
}

// ---------------------------------------------------------------------------
extern "C" void kernel_launch(void* const* d_in, const int* in_sizes, int n_in,
                              void* d_out, int out_size) {
    const float* x        = (const float*)d_in[0];
    const float* rope_cos = (const float*)d_in[2];
    const float* rope_sin = (const float*)d_in[3];
    const float* Wq       = (const float*)d_in[4];
    const float* Wk       = (const float*)d_in[5];
    const float* Wv       = (const float*)d_in[6];
    const float* Wo       = (const float*)d_in[7];
    const float* q_scale  = (const float*)d_in[8];
    const float* k_scale  = (const float*)d_in[9];
    float* out = (float*)d_out;

    char* base;
    cudaGetSymbolAddress((void**)&base, g_arena);
    size_t cur = 0;
    auto alloc = [&](size_t bytes) { char* p = base + cur; cur += (bytes + 255) & ~255ULL; return p; };

    float* Qf  = (float*)alloc((size_t)MROWS * D * 4);
    float* Kf  = (float*)alloc((size_t)MROWS * KVD * 4);
    float* Of  = (float*)alloc((size_t)MROWS * D * 4);
    bf16* Qhh  = (bf16*)alloc((size_t)MROWS * D * 2);
    bf16* Qll  = (bf16*)alloc((size_t)MROWS * D * 2);
    bf16* Khh  = (bf16*)alloc((size_t)MROWS * KVD * 2);
    bf16* Kll  = (bf16*)alloc((size_t)MROWS * KVD * 2);
    bf16* Vhh  = (bf16*)alloc((size_t)MROWS * KVD * 2);
    bf16* Vll  = (bf16*)alloc((size_t)MROWS * KVD * 2);
    char* xq0  = alloc((size_t)MROWS * D);
    char* xq1  = alloc((size_t)MROWS * D);
    char* Oq0  = alloc((size_t)MROWS * D);
    char* Oq1  = alloc((size_t)MROWS * D);
    float* WTp = (float*)alloc((size_t)NFUSE * D * 4);   // packed QKV W^T fp32
    float* WoT = (float*)alloc((size_t)D * D * 4);
    char* Wp0  = alloc((size_t)NFUSE * D);
    char* Wp1  = alloc((size_t)NFUSE * D);
    char* Wo0  = alloc((size_t)D * D);
    char* Wo1  = alloc((size_t)D * D);
    float* sx  = (float*)alloc((size_t)MROWS * 4);
    float* sO  = (float*)alloc((size_t)MROWS * 4);
    float* sWp = (float*)alloc((size_t)NFUSE * 4);
    float* sWo = (float*)alloc((size_t)D * 4);

    cudaFuncSetAttribute(gemm_s8, cudaFuncAttributeMaxDynamicSharedMemorySize, GEMM_SMEM);
    cudaFuncSetAttribute(attn_mma, cudaFuncAttributeMaxDynamicSharedMemorySize, ATTN_SMEM);

    dim3 thr(256);
    // weight prepasses
    transp32<<<dim3(D / 32, D / 32), dim3(32, 8)>>>(Wq, WTp, D, D, 0);
    transp32<<<dim3(KVD / 32, D / 32), dim3(32, 8)>>>(Wk, WTp, D, KVD, 1024);
    transp32<<<dim3(KVD / 32, D / 32), dim3(32, 8)>>>(Wv, WTp, D, KVD, 1280);
    transp32<<<dim3(D / 32, D / 32), dim3(32, 8)>>>(Wo, WoT, D, D, 0);
    quant_rows<<<NFUSE / 8, thr>>>(WTp, Wp0, Wp1, sWp, NFUSE);
    quant_rows<<<D / 8, thr>>>(WoT, Wo0, Wo1, sWo, D);
    // activation quantization
    quant_rows<<<MROWS / 8, thr>>>(x, xq0, xq1, sx, MROWS);

    // fused QKV projection (int8 2-slice)
    gemm_s8<<<dim3(NFUSE / 128, MROWS / 128), thr, GEMM_SMEM>>>(
        xq0, xq1, sx, Wp0, Wp1, sWp, Qf, Kf, Vhh, Vll, MROWS, NFUSE, D, 2);

    // rmsnorm + rope -> bf16 splits
    rmsrope_kernel<<<(262144 + 65536) / 8, thr>>>(
        Qf, Kf, Qhh, Qll, Khh, Kll, rope_cos, rope_sin, q_scale, k_scale);

    // attention (bf16x3 HMMA) -> fp32 O
    attn_mma<<<NB * NH, thr, ATTN_SMEM>>>(Qhh, Qll, Khh, Kll, Vhh, Vll, Of);

    // quantize O, output projection
    quant_rows<<<MROWS / 8, thr>>>(Of, Oq0, Oq1, sO, MROWS);
    gemm_s8<<<dim3(D / 128, MROWS / 128), thr, GEMM_SMEM>>>(
        Oq0, Oq1, sO, Wo0, Wo1, sWo, out, nullptr, nullptr, nullptr, MROWS, D, D, 0);
}

// round 12
// speedup vs baseline: 2.4706x; 2.4661x over previous
#include <cuda_runtime.h>
#include <cuda_bf16.h>
#include <cuda_fp16.h>
#include <math.h>

#define NB 64
#define S 256
#define D 1024
#define NH 16
#define NKV 4
#define HD 64
#define NIMG 240
#define MROWS (NB * S)       // 16384
#define KVD (NKV * HD)       // 256
#define NFUSE 1536           // packed QKV output columns

typedef __nv_bfloat16 bf16;
typedef __half fp16;

#define ARENA_BYTES 420000000ULL
__device__ __align__(256) char g_arena[ARENA_BYTES];

// ---------------------------------------------------------------------------
// helpers
// ---------------------------------------------------------------------------
__device__ __forceinline__ unsigned smem_u32(const void* p) {
    unsigned a;
    asm("{ .reg .u64 t; cvta.to.shared.u64 t, %1; cvt.u32.u64 %0, t; }" : "=r"(a) : "l"(p));
    return a;
}
__device__ __forceinline__ void cpa16(unsigned saddr, const void* g) {
    asm volatile("cp.async.cg.shared.global [%0], [%1], 16;" :: "r"(saddr), "l"(g));
}
#define CP_COMMIT() asm volatile("cp.async.commit_group;")
#define CP_WAIT1()  asm volatile("cp.async.wait_group 1;")
#define CP_WAIT0()  asm volatile("cp.async.wait_group 0;")

__device__ __forceinline__ unsigned pack_bf16(bf16 a, bf16 b) {
    return (unsigned)__bfloat16_as_ushort(a) | ((unsigned)__bfloat16_as_ushort(b) << 16);
}
__device__ __forceinline__ void split_bf16(float x, bf16& h, bf16& l) {
    h = __float2bfloat16_rn(x);
    l = __float2bfloat16_rn(x - __bfloat162float(h));
}
__device__ __forceinline__ unsigned pack_fp16(fp16 a, fp16 b) {
    return (unsigned)__half_as_ushort(a) | ((unsigned)__half_as_ushort(b) << 16);
}
__device__ __forceinline__ void split_fp16(float x, fp16& h, fp16& l) {
    h = __float2half_rn(x);
    l = __float2half_rn(x - __half2float(h));
}
// bf16 MMA (attention path)
__device__ __forceinline__ void mma16816(float c[4], const unsigned a[4],
                                         unsigned b0, unsigned b1) {
    asm volatile(
        "mma.sync.aligned.m16n8k16.row.col.f32.bf16.bf16.f32 "
        "{%0,%1,%2,%3}, {%4,%5,%6,%7}, {%8,%9}, {%0,%1,%2,%3};"
        : "+f"(c[0]), "+f"(c[1]), "+f"(c[2]), "+f"(c[3])
        : "r"(a[0]), "r"(a[1]), "r"(a[2]), "r"(a[3]), "r"(b0), "r"(b1));
}
// fp16 MMA (GEMM path)
__device__ __forceinline__ void mma16816h(float c[4], const unsigned a[4],
                                          unsigned b0, unsigned b1) {
    asm volatile(
        "mma.sync.aligned.m16n8k16.row.col.f32.f16.f16.f32 "
        "{%0,%1,%2,%3}, {%4,%5,%6,%7}, {%8,%9}, {%0,%1,%2,%3};"
        : "+f"(c[0]), "+f"(c[1]), "+f"(c[2]), "+f"(c[3])
        : "r"(a[0]), "r"(a[1]), "r"(a[2]), "r"(a[3]), "r"(b0), "r"(b1));
}
__device__ __forceinline__ void ldm_x4(unsigned r[4], unsigned addr) {
    asm volatile("ldmatrix.sync.aligned.m8n8.x4.shared.b16 {%0,%1,%2,%3}, [%4];"
                 : "=r"(r[0]), "=r"(r[1]), "=r"(r[2]), "=r"(r[3]) : "r"(addr));
}
__device__ __forceinline__ void ldm_x2(unsigned& r0, unsigned& r1, unsigned addr) {
    asm volatile("ldmatrix.sync.aligned.m8n8.x2.shared.b16 {%0,%1}, [%2];"
                 : "=r"(r0), "=r"(r1) : "r"(addr));
}
__device__ __forceinline__ void ldm_x2t(unsigned& r0, unsigned& r1, unsigned addr) {
    asm volatile("ldmatrix.sync.aligned.m8n8.x2.trans.shared.b16 {%0,%1}, [%2];"
                 : "=r"(r0), "=r"(r1) : "r"(addr));
}

// ---------------------------------------------------------------------------
// Prepass: elementwise fp32 -> fp16 hi/lo split (x and attention-O)
// ---------------------------------------------------------------------------
__global__ void __launch_bounds__(256)
split_x_fp16(const float* __restrict__ x, fp16* __restrict__ xh,
             fp16* __restrict__ xl, int total4) {
    int i4 = blockIdx.x * 256 + threadIdx.x;
    if (i4 >= total4) return;
    int i = i4 * 4;
    float4 v = *(const float4*)(x + i);
    fp16 h0, l0, h1, l1, h2, l2, h3, l3;
    split_fp16(v.x, h0, l0); split_fp16(v.y, h1, l1);
    split_fp16(v.z, h2, l2); split_fp16(v.w, h3, l3);
    *(uint2*)(xh + i) = make_uint2(pack_fp16(h0, h1), pack_fp16(h2, h3));
    *(uint2*)(xl + i) = make_uint2(pack_fp16(l0, l1), pack_fp16(l2, l3));
}

// ---------------------------------------------------------------------------
// Prepass: weight transpose + fp16 convert: W[k][n] -> T[rowOff + n][k]
// ---------------------------------------------------------------------------
__global__ void __launch_bounds__(256)
transp_half(const float* __restrict__ W, fp16* __restrict__ T,
            int Kd, int Nd, int rowOff) {
    __shared__ float t[32][33];
    const int n0 = blockIdx.x * 32, k0 = blockIdx.y * 32;
    const int tx = threadIdx.x, ty = threadIdx.y;   // 32 x 8
    #pragma unroll
    for (int i = 0; i < 4; i++)
        t[ty + 8 * i][tx] = W[(size_t)(k0 + ty + 8 * i) * Nd + n0 + tx];
    __syncthreads();
    #pragma unroll
    for (int i = 0; i < 4; i++)
        T[(size_t)(rowOff + n0 + ty + 8 * i) * Kd + k0 + tx] =
            __float2half_rn(t[tx][ty + 8 * i]);
}

// ---------------------------------------------------------------------------
// fp16 2-pass GEMM: C = A @ B^T,  A = Ah + Al (fp16 h/l), B = Bh (fp16).
// C ~= Ah*Bh + Al*Bh  (weight-side rounding is the only surviving error).
// CTA 128x128, BK=32, cp.async double buffer, 8 warps (2x4), warp 64x32.
// mode 0: C fp32 stride N.
// mode 2: fused QKV routing (cols<1024 -> C fp32 stride D; <1280 -> C2 fp32
//         stride KVD; else -> Ch/Cl bf16 split stride KVD).
// ---------------------------------------------------------------------------
#define GTB (128 * 80)              // tile bytes: 128 rows x 80B pitch (64B data)
#define GEMM_SMEM (2 * 3 * GTB)     // 61440

__global__ void __launch_bounds__(256)
gemm_fp16(const fp16* __restrict__ Agh, const fp16* __restrict__ Agl,
          const fp16* __restrict__ Bgh,
          float* __restrict__ C, float* __restrict__ C2,
          bf16* __restrict__ Ch, bf16* __restrict__ Cl,
          int M, int N, int K, int mode) {
    extern __shared__ char smg[];
    const unsigned sb = smem_u32(smg);
    const int tid = threadIdx.x;
    const int wid = tid >> 5;
    const int lane = tid & 31;
    const int lr = lane >> 2, lc = lane & 3;

    const int bm = blockIdx.y * 128;
    const int bn = blockIdx.x * 128;
    const int wm = (wid >> 2) * 64;
    const int wn = (wid & 3) * 32;

    // cp.async staging: thread covers 32B of one row (two 16B chunks)
    const int srow = tid >> 1, shalf = tid & 1;
    const size_t gaBase = (size_t)(bm + srow) * K + shalf * 16;  // elements
    const size_t gbBase = (size_t)(bn + srow) * K + shalf * 16;
    const unsigned soff = srow * 80 + shalf * 32;                // bytes

    // ldmatrix per-lane byte bases within a tile
    const unsigned aBase = (unsigned)((wm + (lane & 7) + ((lane >> 3) & 1) * 8) * 80
                                      + ((lane >> 4) & 1) * 16);
    const unsigned bBase = (unsigned)((wn + (lane & 7)) * 80 + ((lane >> 3) & 1) * 16);

    float c[4][4][4] = {};
    const int NCH = K / 32;

    // prologue: stage chunk 0 into stage 0
    {
        unsigned base = sb + soff;
        cpa16(base,                Agh + gaBase);
        cpa16(base + 16,           Agh + gaBase + 8);
        cpa16(base + GTB,          Agl + gaBase);
        cpa16(base + GTB + 16,     Agl + gaBase + 8);
        cpa16(base + 2 * GTB,      Bgh + gbBase);
        cpa16(base + 2 * GTB + 16, Bgh + gbBase + 8);
        CP_COMMIT();
    }

    for (int ch = 0; ch < NCH; ch++) {
        const int s = ch & 1;
        if (ch + 1 < NCH) {
            unsigned base = sb + (s ^ 1) * 3 * GTB + soff;
            size_t ka = gaBase + (size_t)(ch + 1) * 32;
            size_t kb = gbBase + (size_t)(ch + 1) * 32;
            cpa16(base,                Agh + ka);
            cpa16(base + 16,           Agh + ka + 8);
            cpa16(base + GTB,          Agl + ka);
            cpa16(base + GTB + 16,     Agl + ka + 8);
            cpa16(base + 2 * GTB,      Bgh + kb);
            cpa16(base + 2 * GTB + 16, Bgh + kb + 8);
            CP_COMMIT();
            CP_WAIT1();
        } else {
            CP_WAIT0();
        }
        __syncthreads();

        const unsigned uAh = sb + s * 3 * GTB;
        const unsigned uAl = uAh + GTB;
        const unsigned uBh = uAh + 2 * GTB;

        #pragma unroll
        for (int ks = 0; ks < 2; ks++) {
            const unsigned ko = ks * 32;   // 16 elems = 32 bytes
            unsigned ah[4][4], al[4][4], bh[4][2];
            #pragma unroll
            for (int mi = 0; mi < 4; mi++) {
                unsigned adr = aBase + mi * 16 * 80 + ko;
                ldm_x4(ah[mi], uAh + adr);
                ldm_x4(al[mi], uAl + adr);
            }
            #pragma unroll
            for (int ni = 0; ni < 4; ni++) {
                unsigned adr = bBase + ni * 8 * 80 + ko;
                ldm_x2(bh[ni][0], bh[ni][1], uBh + adr);
            }
            #pragma unroll
            for (int mi = 0; mi < 4; mi++)
                #pragma unroll
                for (int ni = 0; ni < 4; ni++)
                    mma16816h(c[mi][ni], ah[mi], bh[ni][0], bh[ni][1]);
            #pragma unroll
            for (int mi = 0; mi < 4; mi++)
                #pragma unroll
                for (int ni = 0; ni < 4; ni++)
                    mma16816h(c[mi][ni], al[mi], bh[ni][0], bh[ni][1]);
        }
        __syncthreads();
    }

    // ---- epilogue ----
    if (mode == 0) {
        #pragma unroll
        for (int mi = 0; mi < 4; mi++)
            #pragma unroll
            for (int ni = 0; ni < 4; ni++) {
                int r = bm + wm + mi * 16 + lr;
                int col = bn + wn + ni * 8 + lc * 2;
                *(float2*)&C[(size_t)r * N + col] = make_float2(c[mi][ni][0], c[mi][ni][1]);
                *(float2*)&C[(size_t)(r + 8) * N + col] = make_float2(c[mi][ni][2], c[mi][ni][3]);
            }
    } else {
        if (bn < 1024) {
            #pragma unroll
            for (int mi = 0; mi < 4; mi++)
                #pragma unroll
                for (int ni = 0; ni < 4; ni++) {
                    int r = bm + wm + mi * 16 + lr;
                    int col = bn + wn + ni * 8 + lc * 2;
                    *(float2*)&C[(size_t)r * D + col] = make_float2(c[mi][ni][0], c[mi][ni][1]);
                    *(float2*)&C[(size_t)(r + 8) * D + col] = make_float2(c[mi][ni][2], c[mi][ni][3]);
                }
        } else if (bn < 1280) {
            #pragma unroll
            for (int mi = 0; mi < 4; mi++)
                #pragma unroll
                for (int ni = 0; ni < 4; ni++) {
                    int r = bm + wm + mi * 16 + lr;
                    int col = (bn - 1024) + wn + ni * 8 + lc * 2;
                    *(float2*)&C2[(size_t)r * KVD + col] = make_float2(c[mi][ni][0], c[mi][ni][1]);
                    *(float2*)&C2[(size_t)(r + 8) * KVD + col] = make_float2(c[mi][ni][2], c[mi][ni][3]);
                }
        } else {
            unsigned* Oh32 = (unsigned*)Ch;
            unsigned* Ol32 = (unsigned*)Cl;
            #pragma unroll
            for (int mi = 0; mi < 4; mi++)
                #pragma unroll
                for (int ni = 0; ni < 4; ni++) {
                    int r = bm + wm + mi * 16 + lr;
                    int col = (bn - 1280) + wn + ni * 8 + lc * 2;
                    bf16 h0, l0, h1, l1;
                    split_bf16(c[mi][ni][0], h0, l0);
                    split_bf16(c[mi][ni][1], h1, l1);
                    Oh32[((size_t)r * KVD + col) >> 1] = pack_bf16(h0, h1);
                    Ol32[((size_t)r * KVD + col) >> 1] = pack_bf16(l0, l1);
                    split_bf16(c[mi][ni][2], h0, l0);
                    split_bf16(c[mi][ni][3], h1, l1);
                    Oh32[((size_t)(r + 8) * KVD + col) >> 1] = pack_bf16(h0, h1);
                    Ol32[((size_t)(r + 8) * KVD + col) >> 1] = pack_bf16(l0, l1);
                }
        }
    }
}

// ---------------------------------------------------------------------------
// RMSNorm + RoPE: fp32 Q/K in, bf16 hi/lo out (unchanged)
// ---------------------------------------------------------------------------
__global__ void __launch_bounds__(256)
rmsrope_kernel(const float* __restrict__ Qf, const float* __restrict__ Kf,
               bf16* __restrict__ Qh, bf16* __restrict__ Ql,
               bf16* __restrict__ Kh, bf16* __restrict__ Kl,
               const float* __restrict__ rope_cos, const float* __restrict__ rope_sin,
               const float* __restrict__ q_scale, const float* __restrict__ k_scale) {
    const int w = blockIdx.x * 8 + (threadIdx.x >> 5);
    const int lane = threadIdx.x & 31;

    const float* p;
    bf16 *oh, *ol;
    const float* scale;
    int s_idx;
    size_t base;
    if (w < 262144) {
        int ns = w >> 4;
        int h = w & 15;
        base = (size_t)ns * D + h * HD;
        p = Qf + base; oh = Qh + base; ol = Ql + base;
        scale = q_scale;
        s_idx = ns & 255;
    } else {
        int w2 = w - 262144;
        int ns = w2 >> 2;
        int h = w2 & 3;
        base = (size_t)ns * KVD + h * HD;
        p = Kf + base; oh = Kh + base; ol = Kl + base;
        scale = k_scale;
        s_idx = ns & 255;
    }

    float v1 = p[lane];
    float v2 = p[lane + 32];
    float ss = v1 * v1 + v2 * v2;
    #pragma unroll
    for (int o = 16; o; o >>= 1) ss += __shfl_xor_sync(0xffffffffu, ss, o);
    float r = rsqrtf(ss * (1.0f / 64.0f) + 1e-6f);

    float a = v1 * r * scale[lane];
    float b = v2 * r * scale[lane + 32];
    float cc = rope_cos[s_idx * 32 + lane];
    float sn = rope_sin[s_idx * 32 + lane];
    float r1 = a * cc - b * sn;
    float r2 = b * cc + a * sn;
    bf16 h, l;
    split_bf16(r1, h, l);
    oh[lane] = h; ol[lane] = l;
    split_bf16(r2, h, l);
    oh[lane + 32] = h; ol[lane + 32] = l;
}

// ---------------------------------------------------------------------------
// Flash-attention bf16x3 HMMA kernel; writes fp32 O (unchanged, proven)
// ---------------------------------------------------------------------------
#define KVP 72
#define ATTN_SMEM (4 * 256 * KVP * 2)

__global__ void __launch_bounds__(256, 1)
attn_mma(const bf16* __restrict__ Qh, const bf16* __restrict__ Ql,
         const bf16* __restrict__ Kh, const bf16* __restrict__ Kl,
         const bf16* __restrict__ Vh, const bf16* __restrict__ Vl,
         float* __restrict__ Of) {
    extern __shared__ char sma[];
    bf16* sKh = (bf16*)sma;
    bf16* sKl = sKh + 256 * KVP;
    bf16* sVh = sKl + 256 * KVP;
    bf16* sVl = sVh + 256 * KVP;

    const int bid = blockIdx.x;
    const int n = bid >> 4;
    const int h = bid & 15;
    const int hkv = h >> 2;
    const int tid = threadIdx.x;
    const int w = tid >> 5;
    const int lane = tid & 31;
    const int lr = lane >> 2, lc = lane & 3;

    {
        const bf16* srcs[4] = {Kh, Kl, Vh, Vl};
        bf16* dsts[4] = {sKh, sKl, sVh, sVl};
        #pragma unroll
        for (int a = 0; a < 4; a++) {
            const char* src = (const char*)(srcs[a] + (size_t)n * 256 * KVD + hkv * HD);
            char* dst = (char*)dsts[a];
            for (int it = tid; it < 2048; it += 256) {
                int row = it >> 3, q = it & 7;
                *(uint4*)(dst + row * (KVP * 2) + q * 16) =
                    *(const uint4*)(src + (size_t)row * (KVD * 2) + q * 16);
            }
        }
    }
    __syncthreads();

    const unsigned uKh = smem_u32(sKh), uKl = smem_u32(sKl);
    const unsigned uVh = smem_u32(sVh), uVl = smem_u32(sVl);
    const unsigned* Q32h = (const unsigned*)Qh;
    const unsigned* Q32l = (const unsigned*)Ql;

    const int wq0 = w * 32;
    float o[2][8][4] = {};
    float mrun[2][2] = {{-3e38f, -3e38f}, {-3e38f, -3e38f}};
    float lrun[2][2] = {{0.f, 0.f}, {0.f, 0.f}};

    for (int j = 0; j < 4; j++) {
        float c[2][8][4] = {};

        #pragma unroll
        for (int kt = 0; kt < 4; kt++) {
            unsigned qh[2][4], ql[2][4];
            #pragma unroll
            for (int mt = 0; mt < 2; mt++) {
                size_t row = (size_t)n * 256 + wq0 + mt * 16 + lr;
                size_t b0 = row * 512 + h * 32 + kt * 8 + lc;
                qh[mt][0] = Q32h[b0];
                qh[mt][1] = Q32h[b0 + 8 * 512];
                qh[mt][2] = Q32h[b0 + 4];
                qh[mt][3] = Q32h[b0 + 8 * 512 + 4];
                ql[mt][0] = Q32l[b0];
                ql[mt][1] = Q32l[b0 + 8 * 512];
                ql[mt][2] = Q32l[b0 + 4];
                ql[mt][3] = Q32l[b0 + 8 * 512 + 4];
            }
            #pragma unroll
            for (int nt = 0; nt < 8; nt++) {
                int krow = j * 64 + nt * 8 + (lane & 7);
                int kcol = kt * 16 + ((lane >> 3) & 1) * 8;
                unsigned adr = (unsigned)(krow * KVP + kcol) * 2;
                unsigned kh0, kh1, kl0, kl1;
                ldm_x2(kh0, kh1, uKh + adr);
                ldm_x2(kl0, kl1, uKl + adr);
                #pragma unroll
                for (int mt = 0; mt < 2; mt++) {
                    mma16816(c[mt][nt], qh[mt], kh0, kh1);
                    mma16816(c[mt][nt], qh[mt], kl0, kl1);
                    mma16816(c[mt][nt], ql[mt], kh0, kh1);
                }
            }
        }

        #pragma unroll
        for (int mt = 0; mt < 2; mt++) {
            #pragma unroll
            for (int half = 0; half < 2; half++) {
                const int qr = wq0 + mt * 16 + lr + 8 * half;
                float bmax = -3e38f;
                #pragma unroll
                for (int nt = 0; nt < 8; nt++) {
                    #pragma unroll
                    for (int e = 0; e < 2; e++) {
                        float s = c[mt][nt][2 * half + e] * 0.125f;
                        float t = __expf(s * 0.04f);
                        s = 50.0f * __fdividef(t - 1.0f, t + 1.0f);
                        int col = j * 64 + nt * 8 + 2 * lc + e;
                        if (!((qr >= NIMG) || (col < NIMG))) s = -3e38f;
                        c[mt][nt][2 * half + e] = s;
                        bmax = fmaxf(bmax, s);
                    }
                }
                bmax = fmaxf(bmax, __shfl_xor_sync(0xffffffffu, bmax, 1));
                bmax = fmaxf(bmax, __shfl_xor_sync(0xffffffffu, bmax, 2));
                float mold = mrun[mt][half];
                float mnew = fmaxf(mold, bmax);
                float resc = __expf(mold - mnew);
                float rs = 0.0f;
                #pragma unroll
                for (int nt = 0; nt < 8; nt++) {
                    #pragma unroll
                    for (int e = 0; e < 2; e++) {
                        float p = __expf(c[mt][nt][2 * half + e] - mnew);
                        c[mt][nt][2 * half + e] = p;
                        rs += p;
                    }
                }
                rs += __shfl_xor_sync(0xffffffffu, rs, 1);
                rs += __shfl_xor_sync(0xffffffffu, rs, 2);
                lrun[mt][half] = lrun[mt][half] * resc + rs;
                mrun[mt][half] = mnew;
                #pragma unroll
                for (int dt = 0; dt < 8; dt++) {
                    o[mt][dt][2 * half]     *= resc;
                    o[mt][dt][2 * half + 1] *= resc;
                }
            }
        }

        #pragma unroll
        for (int kt = 0; kt < 4; kt++) {
            unsigned ph[2][4], pl[2][4];
            #pragma unroll
            for (int mt = 0; mt < 2; mt++) {
                bf16 h0, l0, h1, l1;
                split_bf16(c[mt][2 * kt][0], h0, l0);
                split_bf16(c[mt][2 * kt][1], h1, l1);
                ph[mt][0] = pack_bf16(h0, h1); pl[mt][0] = pack_bf16(l0, l1);
                split_bf16(c[mt][2 * kt][2], h0, l0);
                split_bf16(c[mt][2 * kt][3], h1, l1);
                ph[mt][1] = pack_bf16(h0, h1); pl[mt][1] = pack_bf16(l0, l1);
                split_bf16(c[mt][2 * kt + 1][0], h0, l0);
                split_bf16(c[mt][2 * kt + 1][1], h1, l1);
                ph[mt][2] = pack_bf16(h0, h1); pl[mt][2] = pack_bf16(l0, l1);
                split_bf16(c[mt][2 * kt + 1][2], h0, l0);
                split_bf16(c[mt][2 * kt + 1][3], h1, l1);
                ph[mt][3] = pack_bf16(h0, h1); pl[mt][3] = pack_bf16(l0, l1);
            }
            #pragma unroll
            for (int dt = 0; dt < 8; dt++) {
                int vrow = j * 64 + kt * 16 + (lane & 15);
                unsigned adr = (unsigned)(vrow * KVP + dt * 8) * 2;
                unsigned vh0, vh1, vl0, vl1;
                ldm_x2t(vh0, vh1, uVh + adr);
                ldm_x2t(vl0, vl1, uVl + adr);
                #pragma unroll
                for (int mt = 0; mt < 2; mt++) {
                    mma16816(o[mt][dt], ph[mt], vh0, vh1);
                    mma16816(o[mt][dt], ph[mt], vl0, vl1);
                    mma16816(o[mt][dt], pl[mt], vh0, vh1);
                }
            }
        }
    }

    #pragma unroll
    for (int mt = 0; mt < 2; mt++) {
        float inv0 = __fdividef(1.0f, lrun[mt][0]);
        float inv1 = __fdividef(1.0f, lrun[mt][1]);
        size_t r0 = (size_t)n * 256 + wq0 + mt * 16 + lr;
        #pragma unroll
        for (int dt = 0; dt < 8; dt++) {
            size_t i0 = r0 * 1024 + h * 64 + dt * 8 + lc * 2;
            *(float2*)&Of[i0] = make_float2(o[mt][dt][0] * inv0, o[mt][dt][1] * inv0);
            size_t i1 = (r0 + 8) * 1024 + h * 64 + dt * 8 + lc * 2;
            *(float2*)&Of[i1] = make_float2(o[mt][dt][2] * inv1, o[mt][dt][3] * inv1);
        }
    }
}

// ---------------------------------------------------------------------------
extern "C" void kernel_launch(void* const* d_in, const int* in_sizes, int n_in,
                              void* d_out, int out_size) {
    const float* x        = (const float*)d_in[0];
    const float* rope_cos = (const float*)d_in[2];
    const float* rope_sin = (const float*)d_in[3];
    const float* Wq       = (const float*)d_in[4];
    const float* Wk       = (const float*)d_in[5];
    const float* Wv       = (const float*)d_in[6];
    const float* Wo       = (const float*)d_in[7];
    const float* q_scale  = (const float*)d_in[8];
    const float* k_scale  = (const float*)d_in[9];
    float* out = (float*)d_out;

    char* base;
    cudaGetSymbolAddress((void**)&base, g_arena);
    size_t cur = 0;
    auto alloc = [&](size_t bytes) { char* p = base + cur; cur += (bytes + 255) & ~255ULL; return p; };

    float* Qf  = (float*)alloc((size_t)MROWS * D * 4);
    float* Kf  = (float*)alloc((size_t)MROWS * KVD * 4);
    float* Of  = (float*)alloc((size_t)MROWS * D * 4);
    bf16* Qhh  = (bf16*)alloc((size_t)MROWS * D * 2);
    bf16* Qll  = (bf16*)alloc((size_t)MROWS * D * 2);
    bf16* Khh  = (bf16*)alloc((size_t)MROWS * KVD * 2);
    bf16* Kll  = (bf16*)alloc((size_t)MROWS * KVD * 2);
    bf16* Vhh  = (bf16*)alloc((size_t)MROWS * KVD * 2);
    bf16* Vll  = (bf16*)alloc((size_t)MROWS * KVD * 2);
    fp16* xh   = (fp16*)alloc((size_t)MROWS * D * 2);
    fp16* xl   = (fp16*)alloc((size_t)MROWS * D * 2);
    fp16* Ohf  = (fp16*)alloc((size_t)MROWS * D * 2);
    fp16* Olf  = (fp16*)alloc((size_t)MROWS * D * 2);
    fp16* WTh  = (fp16*)alloc((size_t)NFUSE * D * 2);   // packed QKV W^T fp16
    fp16* WoTh = (fp16*)alloc((size_t)D * D * 2);

    cudaFuncSetAttribute(gemm_fp16, cudaFuncAttributeMaxDynamicSharedMemorySize, GEMM_SMEM);
    cudaFuncSetAttribute(attn_mma, cudaFuncAttributeMaxDynamicSharedMemorySize, ATTN_SMEM);

    dim3 thr(256);
    // prepasses
    split_x_fp16<<<MROWS * D / 4 / 256, 256>>>(x, xh, xl, MROWS * D / 4);
    transp_half<<<dim3(D / 32, D / 32), dim3(32, 8)>>>(Wq, WTh, D, D, 0);
    transp_half<<<dim3(KVD / 32, D / 32), dim3(32, 8)>>>(Wk, WTh, D, KVD, 1024);
    transp_half<<<dim3(KVD / 32, D / 32), dim3(32, 8)>>>(Wv, WTh, D, KVD, 1280);
    transp_half<<<dim3(D / 32, D / 32), dim3(32, 8)>>>(Wo, WoTh, D, D, 0);

    // fused QKV projection (fp16 2-pass)
    gemm_fp16<<<dim3(NFUSE / 128, MROWS / 128), thr, GEMM_SMEM>>>(
        xh, xl, WTh, Qf, Kf, Vhh, Vll, MROWS, NFUSE, D, 2);

    // rmsnorm + rope -> bf16 splits
    rmsrope_kernel<<<(262144 + 65536) / 8, thr>>>(
        Qf, Kf, Qhh, Qll, Khh, Kll, rope_cos, rope_sin, q_scale, k_scale);

    // attention (bf16x3 HMMA) -> fp32 O
    attn_mma<<<NB * NH, thr, ATTN_SMEM>>>(Qhh, Qll, Khh, Kll, Vhh, Vll, Of);

    // split O to fp16 h/l, output projection (fp16 2-pass)
    split_x_fp16<<<MROWS * D / 4 / 256, 256>>>(Of, Ohf, Olf, MROWS * D / 4);
    gemm_fp16<<<dim3(D / 128, MROWS / 128), thr, GEMM_SMEM>>>(
        Ohf, Olf, WoTh, out, nullptr, nullptr, nullptr, MROWS, D, D, 0);
}

// round 13
// speedup vs baseline: 3.2651x; 1.3216x over previous
#include <cuda_runtime.h>
#include <cuda_bf16.h>
#include <cuda_fp16.h>
#include <math.h>

#define NB 64
#define S 256
#define D 1024
#define NH 16
#define NKV 4
#define HD 64
#define NIMG 240
#define MROWS (NB * S)       // 16384
#define KVD (NKV * HD)       // 256
#define NFUSE 1536           // packed QKV output columns

typedef __nv_bfloat16 bf16;
typedef __half fp16;

#define ARENA_BYTES 420000000ULL
__device__ __align__(256) char g_arena[ARENA_BYTES];

// ---------------------------------------------------------------------------
// helpers
// ---------------------------------------------------------------------------
__device__ __forceinline__ unsigned smem_u32(const void* p) {
    unsigned a;
    asm("{ .reg .u64 t; cvta.to.shared.u64 t, %1; cvt.u32.u64 %0, t; }" : "=r"(a) : "l"(p));
    return a;
}
__device__ __forceinline__ void cpa16(unsigned saddr, const void* g) {
    asm volatile("cp.async.cg.shared.global [%0], [%1], 16;" :: "r"(saddr), "l"(g));
}
#define CP_COMMIT() asm volatile("cp.async.commit_group;")
#define CP_WAIT1()  asm volatile("cp.async.wait_group 1;")
#define CP_WAIT0()  asm volatile("cp.async.wait_group 0;")

__device__ __forceinline__ unsigned pack_fp16(fp16 a, fp16 b) {
    return (unsigned)__half_as_ushort(a) | ((unsigned)__half_as_ushort(b) << 16);
}
__device__ __forceinline__ void split_fp16(float x, fp16& h, fp16& l) {
    h = __float2half_rn(x);
    l = __float2half_rn(x - __half2float(h));
}
__device__ __forceinline__ void mma16816h(float c[4], const unsigned a[4],
                                          unsigned b0, unsigned b1) {
    asm volatile(
        "mma.sync.aligned.m16n8k16.row.col.f32.f16.f16.f32 "
        "{%0,%1,%2,%3}, {%4,%5,%6,%7}, {%8,%9}, {%0,%1,%2,%3};"
        : "+f"(c[0]), "+f"(c[1]), "+f"(c[2]), "+f"(c[3])
        : "r"(a[0]), "r"(a[1]), "r"(a[2]), "r"(a[3]), "r"(b0), "r"(b1));
}
__device__ __forceinline__ void ldm_x4(unsigned r[4], unsigned addr) {
    asm volatile("ldmatrix.sync.aligned.m8n8.x4.shared.b16 {%0,%1,%2,%3}, [%4];"
                 : "=r"(r[0]), "=r"(r[1]), "=r"(r[2]), "=r"(r[3]) : "r"(addr));
}
__device__ __forceinline__ void ldm_x2(unsigned& r0, unsigned& r1, unsigned addr) {
    asm volatile("ldmatrix.sync.aligned.m8n8.x2.shared.b16 {%0,%1}, [%2];"
                 : "=r"(r0), "=r"(r1) : "r"(addr));
}
__device__ __forceinline__ void ldm_x2t(unsigned& r0, unsigned& r1, unsigned addr) {
    asm volatile("ldmatrix.sync.aligned.m8n8.x2.trans.shared.b16 {%0,%1}, [%2];"
                 : "=r"(r0), "=r"(r1) : "r"(addr));
}

// ---------------------------------------------------------------------------
// Prepass: elementwise fp32 -> fp16 hi/lo split (for x)
// ---------------------------------------------------------------------------
__global__ void __launch_bounds__(256)
split_x_fp16(const float* __restrict__ x, fp16* __restrict__ xh,
             fp16* __restrict__ xl, int total4) {
    int i4 = blockIdx.x * 256 + threadIdx.x;
    if (i4 >= total4) return;
    int i = i4 * 4;
    float4 v = *(const float4*)(x + i);
    fp16 h0, l0, h1, l1, h2, l2, h3, l3;
    split_fp16(v.x, h0, l0); split_fp16(v.y, h1, l1);
    split_fp16(v.z, h2, l2); split_fp16(v.w, h3, l3);
    *(uint2*)(xh + i) = make_uint2(pack_fp16(h0, h1), pack_fp16(h2, h3));
    *(uint2*)(xl + i) = make_uint2(pack_fp16(l0, l1), pack_fp16(l2, l3));
}

// ---------------------------------------------------------------------------
// Prepass: weight transpose + fp16 convert: W[k][n] -> T[rowOff + n][k]
// ---------------------------------------------------------------------------
__global__ void __launch_bounds__(256)
transp_half(const float* __restrict__ W, fp16* __restrict__ T,
            int Kd, int Nd, int rowOff) {
    __shared__ float t[32][33];
    const int n0 = blockIdx.x * 32, k0 = blockIdx.y * 32;
    const int tx = threadIdx.x, ty = threadIdx.y;   // 32 x 8
    #pragma unroll
    for (int i = 0; i < 4; i++)
        t[ty + 8 * i][tx] = W[(size_t)(k0 + ty + 8 * i) * Nd + n0 + tx];
    __syncthreads();
    #pragma unroll
    for (int i = 0; i < 4; i++)
        T[(size_t)(rowOff + n0 + ty + 8 * i) * Kd + k0 + tx] =
            __float2half_rn(t[tx][ty + 8 * i]);
}

// ---------------------------------------------------------------------------
// fp16 GEMM, precision-asymmetric:
// 2-pass (Ah+Al)*Bh where output feeds the direct path; 1-pass Ah*Bh where
// output is softmax-protected (QKV mode, cols < 1280).
// CTA 128x128, BK=32, cp.async double buffer, 8 warps (2x4), warp 64x32.
// mode 0: C fp32 stride N (2-pass).
// mode 2: fused QKV routing: cols<1024 -> C fp32 stride D (1-pass);
//         <1280 -> C2 fp32 stride KVD (1-pass); else -> Cv fp16 stride KVD (2-pass).
// ---------------------------------------------------------------------------
#define GTB (128 * 80)              // tile bytes: 128 rows x 80B pitch (64B data)
#define GEMM_SMEM (2 * 3 * GTB)     // 61440

__global__ void __launch_bounds__(256)
gemm_fp16(const fp16* __restrict__ Agh, const fp16* __restrict__ Agl,
          const fp16* __restrict__ Bgh,
          float* __restrict__ C, float* __restrict__ C2,
          fp16* __restrict__ Cv,
          int M, int N, int K, int mode) {
    extern __shared__ char smg[];
    const unsigned sb = smem_u32(smg);
    const int tid = threadIdx.x;
    const int wid = tid >> 5;
    const int lane = tid & 31;
    const int lr = lane >> 2, lc = lane & 3;

    const int bm = blockIdx.y * 128;
    const int bn = blockIdx.x * 128;
    const int wm = (wid >> 2) * 64;
    const int wn = (wid & 3) * 32;

    const bool two = (mode == 0) || (bn >= 1280);   // uniform per CTA

    const int srow = tid >> 1, shalf = tid & 1;
    const size_t gaBase = (size_t)(bm + srow) * K + shalf * 16;
    const size_t gbBase = (size_t)(bn + srow) * K + shalf * 16;
    const unsigned soff = srow * 80 + shalf * 32;

    const unsigned aBase = (unsigned)((wm + (lane & 7) + ((lane >> 3) & 1) * 8) * 80
                                      + ((lane >> 4) & 1) * 16);
    const unsigned bBase = (unsigned)((wn + (lane & 7)) * 80 + ((lane >> 3) & 1) * 16);

    float c[4][4][4] = {};
    const int NCH = K / 32;

    // prologue: stage chunk 0 into stage 0
    {
        unsigned base = sb + soff;
        cpa16(base,                Agh + gaBase);
        cpa16(base + 16,           Agh + gaBase + 8);
        if (two) {
            cpa16(base + GTB,      Agl + gaBase);
            cpa16(base + GTB + 16, Agl + gaBase + 8);
        }
        cpa16(base + 2 * GTB,      Bgh + gbBase);
        cpa16(base + 2 * GTB + 16, Bgh + gbBase + 8);
        CP_COMMIT();
    }

    for (int ch = 0; ch < NCH; ch++) {
        const int s = ch & 1;
        if (ch + 1 < NCH) {
            unsigned base = sb + (s ^ 1) * 3 * GTB + soff;
            size_t ka = gaBase + (size_t)(ch + 1) * 32;
            size_t kb = gbBase + (size_t)(ch + 1) * 32;
            cpa16(base,                Agh + ka);
            cpa16(base + 16,           Agh + ka + 8);
            if (two) {
                cpa16(base + GTB,      Agl + ka);
                cpa16(base + GTB + 16, Agl + ka + 8);
            }
            cpa16(base + 2 * GTB,      Bgh + kb);
            cpa16(base + 2 * GTB + 16, Bgh + kb + 8);
            CP_COMMIT();
            CP_WAIT1();
        } else {
            CP_WAIT0();
        }
        __syncthreads();

        const unsigned uAh = sb + s * 3 * GTB;
        const unsigned uAl = uAh + GTB;
        const unsigned uBh = uAh + 2 * GTB;

        #pragma unroll
        for (int ks = 0; ks < 2; ks++) {
            const unsigned ko = ks * 32;
            unsigned ah[4][4], bh[4][2];
            #pragma unroll
            for (int mi = 0; mi < 4; mi++)
                ldm_x4(ah[mi], uAh + aBase + mi * 16 * 80 + ko);
            #pragma unroll
            for (int ni = 0; ni < 4; ni++)
                ldm_x2(bh[ni][0], bh[ni][1], uBh + bBase + ni * 8 * 80 + ko);
            #pragma unroll
            for (int mi = 0; mi < 4; mi++)
                #pragma unroll
                for (int ni = 0; ni < 4; ni++)
                    mma16816h(c[mi][ni], ah[mi], bh[ni][0], bh[ni][1]);
            if (two) {
                unsigned al[4][4];
                #pragma unroll
                for (int mi = 0; mi < 4; mi++)
                    ldm_x4(al[mi], uAl + aBase + mi * 16 * 80 + ko);
                #pragma unroll
                for (int mi = 0; mi < 4; mi++)
                    #pragma unroll
                    for (int ni = 0; ni < 4; ni++)
                        mma16816h(c[mi][ni], al[mi], bh[ni][0], bh[ni][1]);
            }
        }
        __syncthreads();
    }

    // ---- epilogue ----
    if (mode == 0) {
        #pragma unroll
        for (int mi = 0; mi < 4; mi++)
            #pragma unroll
            for (int ni = 0; ni < 4; ni++) {
                int r = bm + wm + mi * 16 + lr;
                int col = bn + wn + ni * 8 + lc * 2;
                *(float2*)&C[(size_t)r * N + col] = make_float2(c[mi][ni][0], c[mi][ni][1]);
                *(float2*)&C[(size_t)(r + 8) * N + col] = make_float2(c[mi][ni][2], c[mi][ni][3]);
            }
    } else {
        if (bn < 1024) {
            #pragma unroll
            for (int mi = 0; mi < 4; mi++)
                #pragma unroll
                for (int ni = 0; ni < 4; ni++) {
                    int r = bm + wm + mi * 16 + lr;
                    int col = bn + wn + ni * 8 + lc * 2;
                    *(float2*)&C[(size_t)r * D + col] = make_float2(c[mi][ni][0], c[mi][ni][1]);
                    *(float2*)&C[(size_t)(r + 8) * D + col] = make_float2(c[mi][ni][2], c[mi][ni][3]);
                }
        } else if (bn < 1280) {
            #pragma unroll
            for (int mi = 0; mi < 4; mi++)
                #pragma unroll
                for (int ni = 0; ni < 4; ni++) {
                    int r = bm + wm + mi * 16 + lr;
                    int col = (bn - 1024) + wn + ni * 8 + lc * 2;
                    *(float2*)&C2[(size_t)r * KVD + col] = make_float2(c[mi][ni][0], c[mi][ni][1]);
                    *(float2*)&C2[(size_t)(r + 8) * KVD + col] = make_float2(c[mi][ni][2], c[mi][ni][3]);
                }
        } else {
            unsigned* V32 = (unsigned*)Cv;
            #pragma unroll
            for (int mi = 0; mi < 4; mi++)
                #pragma unroll
                for (int ni = 0; ni < 4; ni++) {
                    int r = bm + wm + mi * 16 + lr;
                    int col = (bn - 1280) + wn + ni * 8 + lc * 2;
                    V32[((size_t)r * KVD + col) >> 1] =
                        pack_fp16(__float2half_rn(c[mi][ni][0]), __float2half_rn(c[mi][ni][1]));
                    V32[((size_t)(r + 8) * KVD + col) >> 1] =
                        pack_fp16(__float2half_rn(c[mi][ni][2]), __float2half_rn(c[mi][ni][3]));
                }
        }
    }
}

// ---------------------------------------------------------------------------
// RMSNorm + RoPE: fp32 Q/K in, single fp16 out (score path is softmax-damped)
// ---------------------------------------------------------------------------
__global__ void __launch_bounds__(256)
rmsrope_kernel(const float* __restrict__ Qf, const float* __restrict__ Kf,
               fp16* __restrict__ Qo, fp16* __restrict__ Ko,
               const float* __restrict__ rope_cos, const float* __restrict__ rope_sin,
               const float* __restrict__ q_scale, const float* __restrict__ k_scale) {
    const int w = blockIdx.x * 8 + (threadIdx.x >> 5);
    const int lane = threadIdx.x & 31;

    const float* p;
    fp16* op;
    const float* scale;
    int s_idx;
    if (w < 262144) {
        int ns = w >> 4;
        int h = w & 15;
        size_t base = (size_t)ns * D + h * HD;
        p = Qf + base; op = Qo + base;
        scale = q_scale;
        s_idx = ns & 255;
    } else {
        int w2 = w - 262144;
        int ns = w2 >> 2;
        int h = w2 & 3;
        size_t base = (size_t)ns * KVD + h * HD;
        p = Kf + base; op = Ko + base;
        scale = k_scale;
        s_idx = ns & 255;
    }

    float v1 = p[lane];
    float v2 = p[lane + 32];
    float ss = v1 * v1 + v2 * v2;
    #pragma unroll
    for (int o = 16; o; o >>= 1) ss += __shfl_xor_sync(0xffffffffu, ss, o);
    float r = rsqrtf(ss * (1.0f / 64.0f) + 1e-6f);

    float a = v1 * r * scale[lane];
    float b = v2 * r * scale[lane + 32];
    float cc = rope_cos[s_idx * 32 + lane];
    float sn = rope_sin[s_idx * 32 + lane];
    op[lane]      = __float2half_rn(a * cc - b * sn);
    op[lane + 32] = __float2half_rn(b * cc + a * sn);
}

// ---------------------------------------------------------------------------
// Flash-attention fp16 kernel: QK^T 1-pass, PV 2-pass (P split h/l).
// K/V single fp16 in smem. Writes O as fp16 hi/lo for the Wo GEMM.
// ---------------------------------------------------------------------------
#define KVP 72
#define ATTN_SMEM (2 * 256 * KVP * 2)     // 73728 bytes

__global__ void __launch_bounds__(256, 1)
attn_mma(const fp16* __restrict__ Qg, const fp16* __restrict__ Kg,
         const fp16* __restrict__ Vg,
         fp16* __restrict__ Oh, fp16* __restrict__ Ol) {
    extern __shared__ char sma[];
    fp16* sK = (fp16*)sma;
    fp16* sV = sK + 256 * KVP;

    const int bid = blockIdx.x;
    const int n = bid >> 4;
    const int h = bid & 15;
    const int hkv = h >> 2;
    const int tid = threadIdx.x;
    const int w = tid >> 5;
    const int lane = tid & 31;
    const int lr = lane >> 2, lc = lane & 3;

    // ---- stage K/V (single fp16, coalesced uint4) ----
    {
        const fp16* srcs[2] = {Kg, Vg};
        fp16* dsts[2] = {sK, sV};
        #pragma unroll
        for (int a = 0; a < 2; a++) {
            const char* src = (const char*)(srcs[a] + (size_t)n * 256 * KVD + hkv * HD);
            char* dst = (char*)dsts[a];
            for (int it = tid; it < 2048; it += 256) {
                int row = it >> 3, q = it & 7;
                *(uint4*)(dst + row * (KVP * 2) + q * 16) =
                    *(const uint4*)(src + (size_t)row * (KVD * 2) + q * 16);
            }
        }
    }
    __syncthreads();

    const unsigned uK = smem_u32(sK), uV = smem_u32(sV);
    const unsigned* Q32 = (const unsigned*)Qg;

    const int wq0 = w * 32;
    float o[2][8][4] = {};
    float mrun[2][2] = {{-3e38f, -3e38f}, {-3e38f, -3e38f}};
    float lrun[2][2] = {{0.f, 0.f}, {0.f, 0.f}};

    for (int j = 0; j < 4; j++) {
        float c[2][8][4] = {};

        // ===== QK^T (single fp16 pass) =====
        #pragma unroll
        for (int kt = 0; kt < 4; kt++) {
            unsigned qf[2][4];
            #pragma unroll
            for (int mt = 0; mt < 2; mt++) {
                size_t row = (size_t)n * 256 + wq0 + mt * 16 + lr;
                size_t b0 = row * 512 + h * 32 + kt * 8 + lc;
                qf[mt][0] = Q32[b0];
                qf[mt][1] = Q32[b0 + 8 * 512];
                qf[mt][2] = Q32[b0 + 4];
                qf[mt][3] = Q32[b0 + 8 * 512 + 4];
            }
            #pragma unroll
            for (int nt = 0; nt < 8; nt++) {
                int krow = j * 64 + nt * 8 + (lane & 7);
                int kcol = kt * 16 + ((lane >> 3) & 1) * 8;
                unsigned adr = (unsigned)(krow * KVP + kcol) * 2;
                unsigned k0, k1;
                ldm_x2(k0, k1, uK + adr);
                #pragma unroll
                for (int mt = 0; mt < 2; mt++)
                    mma16816h(c[mt][nt], qf[mt], k0, k1);
            }
        }

        // ===== cap + mask + online softmax =====
        #pragma unroll
        for (int mt = 0; mt < 2; mt++) {
            #pragma unroll
            for (int half = 0; half < 2; half++) {
                const int qr = wq0 + mt * 16 + lr + 8 * half;
                float bmax = -3e38f;
                #pragma unroll
                for (int nt = 0; nt < 8; nt++) {
                    #pragma unroll
                    for (int e = 0; e < 2; e++) {
                        float s = c[mt][nt][2 * half + e] * 0.125f;
                        float t = __expf(s * 0.04f);
                        s = 50.0f * __fdividef(t - 1.0f, t + 1.0f);
                        int col = j * 64 + nt * 8 + 2 * lc + e;
                        if (!((qr >= NIMG) || (col < NIMG))) s = -3e38f;
                        c[mt][nt][2 * half + e] = s;
                        bmax = fmaxf(bmax, s);
                    }
                }
                bmax = fmaxf(bmax, __shfl_xor_sync(0xffffffffu, bmax, 1));
                bmax = fmaxf(bmax, __shfl_xor_sync(0xffffffffu, bmax, 2));
                float mold = mrun[mt][half];
                float mnew = fmaxf(mold, bmax);
                float resc = __expf(mold - mnew);
                float rs = 0.0f;
                #pragma unroll
                for (int nt = 0; nt < 8; nt++) {
                    #pragma unroll
                    for (int e = 0; e < 2; e++) {
                        float p = __expf(c[mt][nt][2 * half + e] - mnew);
                        c[mt][nt][2 * half + e] = p;
                        rs += p;
                    }
                }
                rs += __shfl_xor_sync(0xffffffffu, rs, 1);
                rs += __shfl_xor_sync(0xffffffffu, rs, 2);
                lrun[mt][half] = lrun[mt][half] * resc + rs;
                mrun[mt][half] = mnew;
                #pragma unroll
                for (int dt = 0; dt < 8; dt++) {
                    o[mt][dt][2 * half]     *= resc;
                    o[mt][dt][2 * half + 1] *= resc;
                }
            }
        }

        // ===== PV (P split fp16 h/l, V single fp16) =====
        #pragma unroll
        for (int kt = 0; kt < 4; kt++) {
            unsigned ph[2][4], pl[2][4];
            #pragma unroll
            for (int mt = 0; mt < 2; mt++) {
                fp16 h0, l0, h1, l1;
                split_fp16(c[mt][2 * kt][0], h0, l0);
                split_fp16(c[mt][2 * kt][1], h1, l1);
                ph[mt][0] = pack_fp16(h0, h1); pl[mt][0] = pack_fp16(l0, l1);
                split_fp16(c[mt][2 * kt][2], h0, l0);
                split_fp16(c[mt][2 * kt][3], h1, l1);
                ph[mt][1] = pack_fp16(h0, h1); pl[mt][1] = pack_fp16(l0, l1);
                split_fp16(c[mt][2 * kt + 1][0], h0, l0);
                split_fp16(c[mt][2 * kt + 1][1], h1, l1);
                ph[mt][2] = pack_fp16(h0, h1); pl[mt][2] = pack_fp16(l0, l1);
                split_fp16(c[mt][2 * kt + 1][2], h0, l0);
                split_fp16(c[mt][2 * kt + 1][3], h1, l1);
                ph[mt][3] = pack_fp16(h0, h1); pl[mt][3] = pack_fp16(l0, l1);
            }
            #pragma unroll
            for (int dt = 0; dt < 8; dt++) {
                int vrow = j * 64 + kt * 16 + (lane & 15);
                unsigned adr = (unsigned)(vrow * KVP + dt * 8) * 2;
                unsigned v0, v1;
                ldm_x2t(v0, v1, uV + adr);
                #pragma unroll
                for (int mt = 0; mt < 2; mt++) {
                    mma16816h(o[mt][dt], ph[mt], v0, v1);
                    mma16816h(o[mt][dt], pl[mt], v0, v1);
                }
            }
        }
    }

    // ===== epilogue: normalize + fp16 h/l split store =====
    unsigned* O32h = (unsigned*)Oh;
    unsigned* O32l = (unsigned*)Ol;
    #pragma unroll
    for (int mt = 0; mt < 2; mt++) {
        float inv0 = __fdividef(1.0f, lrun[mt][0]);
        float inv1 = __fdividef(1.0f, lrun[mt][1]);
        size_t r0 = (size_t)n * 256 + wq0 + mt * 16 + lr;
        #pragma unroll
        for (int dt = 0; dt < 8; dt++) {
            fp16 h0, l0, h1, l1;
            size_t i0 = r0 * 512 + h * 32 + dt * 4 + lc;
            split_fp16(o[mt][dt][0] * inv0, h0, l0);
            split_fp16(o[mt][dt][1] * inv0, h1, l1);
            O32h[i0] = pack_fp16(h0, h1);
            O32l[i0] = pack_fp16(l0, l1);
            size_t i1 = (r0 + 8) * 512 + h * 32 + dt * 4 + lc;
            split_fp16(o[mt][dt][2] * inv1, h0, l0);
            split_fp16(o[mt][dt][3] * inv1, h1, l1);
            O32h[i1] = pack_fp16(h0, h1);
            O32l[i1] = pack_fp16(l0, l1);
        }
    }
}

// ---------------------------------------------------------------------------
extern "C" void kernel_launch(void* const* d_in, const int* in_sizes, int n_in,
                              void* d_out, int out_size) {
    const float* x        = (const float*)d_in[0];
    const float* rope_cos = (const float*)d_in[2];
    const float* rope_sin = (const float*)d_in[3];
    const float* Wq       = (const float*)d_in[4];
    const float* Wk       = (const float*)d_in[5];
    const float* Wv       = (const float*)d_in[6];
    const float* Wo       = (const float*)d_in[7];
    const float* q_scale  = (const float*)d_in[8];
    const float* k_scale  = (const float*)d_in[9];
    float* out = (float*)d_out;

    char* base;
    cudaGetSymbolAddress((void**)&base, g_arena);
    size_t cur = 0;
    auto alloc = [&](size_t bytes) { char* p = base + cur; cur += (bytes + 255) & ~255ULL; return p; };

    float* Qf  = (float*)alloc((size_t)MROWS * D * 4);
    float* Kf  = (float*)alloc((size_t)MROWS * KVD * 4);
    fp16* xh   = (fp16*)alloc((size_t)MROWS * D * 2);
    fp16* xl   = (fp16*)alloc((size_t)MROWS * D * 2);
    fp16* Q16  = (fp16*)alloc((size_t)MROWS * D * 2);
    fp16* K16  = (fp16*)alloc((size_t)MROWS * KVD * 2);
    fp16* V16  = (fp16*)alloc((size_t)MROWS * KVD * 2);
    fp16* Ohf  = (fp16*)alloc((size_t)MROWS * D * 2);
    fp16* Olf  = (fp16*)alloc((size_t)MROWS * D * 2);
    fp16* WTh  = (fp16*)alloc((size_t)NFUSE * D * 2);
    fp16* WoTh = (fp16*)alloc((size_t)D * D * 2);

    cudaFuncSetAttribute(gemm_fp16, cudaFuncAttributeMaxDynamicSharedMemorySize, GEMM_SMEM);
    cudaFuncSetAttribute(attn_mma, cudaFuncAttributeMaxDynamicSharedMemorySize, ATTN_SMEM);

    dim3 thr(256);
    // prepasses
    split_x_fp16<<<MROWS * D / 4 / 256, 256>>>(x, xh, xl, MROWS * D / 4);
    transp_half<<<dim3(D / 32, D / 32), dim3(32, 8)>>>(Wq, WTh, D, D, 0);
    transp_half<<<dim3(KVD / 32, D / 32), dim3(32, 8)>>>(Wk, WTh, D, KVD, 1024);
    transp_half<<<dim3(KVD / 32, D / 32), dim3(32, 8)>>>(Wv, WTh, D, KVD, 1280);
    transp_half<<<dim3(D / 32, D / 32), dim3(32, 8)>>>(Wo, WoTh, D, D, 0);

    // fused QKV projection (Q,K 1-pass; V 2-pass -> fp16)
    gemm_fp16<<<dim3(NFUSE / 128, MROWS / 128), thr, GEMM_SMEM>>>(
        xh, xl, WTh, Qf, Kf, V16, MROWS, NFUSE, D, 2);

    // rmsnorm + rope -> single fp16
    rmsrope_kernel<<<(262144 + 65536) / 8, thr>>>(
        Qf, Kf, Q16, K16, rope_cos, rope_sin, q_scale, k_scale);

    // attention (fp16: QK 1-pass, PV 2-pass) -> O fp16 h/l
    attn_mma<<<NB * NH, thr, ATTN_SMEM>>>(Q16, K16, V16, Ohf, Olf);

    // output projection (fp16 2-pass)
    gemm_fp16<<<dim3(D / 128, MROWS / 128), thr, GEMM_SMEM>>>(
        Ohf, Olf, WoTh, out, nullptr, nullptr, MROWS, D, D, 0);
}

// round 15
// speedup vs baseline: 4.0231x; 1.2322x over previous
#include <cuda_runtime.h>
#include <cuda_bf16.h>
#include <cuda_fp16.h>
#include <math.h>

#define NB 64
#define S 256
#define D 1024
#define NH 16
#define NKV 4
#define HD 64
#define NIMG 240
#define MROWS (NB * S)       // 16384
#define KVD (NKV * HD)       // 256
#define NFUSE 1536           // packed QKV output columns

typedef __nv_bfloat16 bf16;
typedef __half fp16;

#define ARENA_BYTES 420000000ULL
__device__ __align__(256) char g_arena[ARENA_BYTES];

// ---------------------------------------------------------------------------
// helpers
// ---------------------------------------------------------------------------
__device__ __forceinline__ unsigned smem_u32(const void* p) {
    unsigned a;
    asm("{ .reg .u64 t; cvta.to.shared.u64 t, %1; cvt.u32.u64 %0, t; }" : "=r"(a) : "l"(p));
    return a;
}
__device__ __forceinline__ void cpa16(unsigned saddr, const void* g) {
    asm volatile("cp.async.cg.shared.global [%0], [%1], 16;" :: "r"(saddr), "l"(g));
}
#define CP_COMMIT() asm volatile("cp.async.commit_group;")
#define CP_WAIT1()  asm volatile("cp.async.wait_group 1;")
#define CP_WAIT0()  asm volatile("cp.async.wait_group 0;")

__device__ __forceinline__ unsigned pack_fp16(fp16 a, fp16 b) {
    return (unsigned)__half_as_ushort(a) | ((unsigned)__half_as_ushort(b) << 16);
}
__device__ __forceinline__ void split_fp16(float x, fp16& h, fp16& l) {
    h = __float2half_rn(x);
    l = __float2half_rn(x - __half2float(h));
}
__device__ __forceinline__ void mma16816h(float c[4], const unsigned a[4],
                                          unsigned b0, unsigned b1) {
    asm volatile(
        "mma.sync.aligned.m16n8k16.row.col.f32.f16.f16.f32 "
        "{%0,%1,%2,%3}, {%4,%5,%6,%7}, {%8,%9}, {%0,%1,%2,%3};"
        : "+f"(c[0]), "+f"(c[1]), "+f"(c[2]), "+f"(c[3])
        : "r"(a[0]), "r"(a[1]), "r"(a[2]), "r"(a[3]), "r"(b0), "r"(b1));
}
__device__ __forceinline__ void ldm_x4(unsigned r[4], unsigned addr) {
    asm volatile("ldmatrix.sync.aligned.m8n8.x4.shared.b16 {%0,%1,%2,%3}, [%4];"
                 : "=r"(r[0]), "=r"(r[1]), "=r"(r[2]), "=r"(r[3]) : "r"(addr));
}
__device__ __forceinline__ void ldm_x2(unsigned& r0, unsigned& r1, unsigned addr) {
    asm volatile("ldmatrix.sync.aligned.m8n8.x2.shared.b16 {%0,%1}, [%2];"
                 : "=r"(r0), "=r"(r1) : "r"(addr));
}
__device__ __forceinline__ void ldm_x2t(unsigned& r0, unsigned& r1, unsigned addr) {
    asm volatile("ldmatrix.sync.aligned.m8n8.x2.trans.shared.b16 {%0,%1}, [%2];"
                 : "=r"(r0), "=r"(r1) : "r"(addr));
}

// ---------------------------------------------------------------------------
// Prepass: elementwise fp32 -> fp16 hi/lo split (for x; lo used by V columns)
// ---------------------------------------------------------------------------
__global__ void __launch_bounds__(256)
split_x_fp16(const float* __restrict__ x, fp16* __restrict__ xh,
             fp16* __restrict__ xl, int total4) {
    int i4 = blockIdx.x * 256 + threadIdx.x;
    if (i4 >= total4) return;
    int i = i4 * 4;
    float4 v = *(const float4*)(x + i);
    fp16 h0, l0, h1, l1, h2, l2, h3, l3;
    split_fp16(v.x, h0, l0); split_fp16(v.y, h1, l1);
    split_fp16(v.z, h2, l2); split_fp16(v.w, h3, l3);
    *(uint2*)(xh + i) = make_uint2(pack_fp16(h0, h1), pack_fp16(h2, h3));
    *(uint2*)(xl + i) = make_uint2(pack_fp16(l0, l1), pack_fp16(l2, l3));
}

// ---------------------------------------------------------------------------
// Prepass: weight transpose + fp16 convert: W[k][n] -> T[rowOff + n][k]
// ---------------------------------------------------------------------------
__global__ void __launch_bounds__(256)
transp_half(const float* __restrict__ W, fp16* __restrict__ T,
            int Kd, int Nd, int rowOff) {
    __shared__ float t[32][33];
    const int n0 = blockIdx.x * 32, k0 = blockIdx.y * 32;
    const int tx = threadIdx.x, ty = threadIdx.y;   // 32 x 8
    #pragma unroll
    for (int i = 0; i < 4; i++)
        t[ty + 8 * i][tx] = W[(size_t)(k0 + ty + 8 * i) * Nd + n0 + tx];
    __syncthreads();
    #pragma unroll
    for (int i = 0; i < 4; i++)
        T[(size_t)(rowOff + n0 + ty + 8 * i) * Kd + k0 + tx] =
            __float2half_rn(t[tx][ty + 8 * i]);
}

// ---------------------------------------------------------------------------
// fp16 GEMM, precision-asymmetric:
// mode 0: 2-pass (Ah+Al)*Bh -> C fp32 stride N.
// mode 1: 1-pass Ah*Bh      -> C fp32 stride N.        (Wo: O-side fp16 ok)
// mode 2: fused QKV routing: cols<1024 -> C fp32 stride D (1-pass);
//         <1280 -> C2 fp32 stride KVD (1-pass); else -> Cv fp16 (2-pass).
// CTA 128x128, BK=32, cp.async double buffer, 8 warps (2x4), warp 64x32.
// ---------------------------------------------------------------------------
#define GTB (128 * 80)              // tile bytes: 128 rows x 80B pitch (64B data)
#define GEMM_SMEM (2 * 3 * GTB)     // 61440

__global__ void __launch_bounds__(256)
gemm_fp16(const fp16* __restrict__ Agh, const fp16* __restrict__ Agl,
          const fp16* __restrict__ Bgh,
          float* __restrict__ C, float* __restrict__ C2,
          fp16* __restrict__ Cv,
          int M, int N, int K, int mode) {
    extern __shared__ char smg[];
    const unsigned sb = smem_u32(smg);
    const int tid = threadIdx.x;
    const int wid = tid >> 5;
    const int lane = tid & 31;
    const int lr = lane >> 2, lc = lane & 3;

    const int bm = blockIdx.y * 128;
    const int bn = blockIdx.x * 128;
    const int wm = (wid >> 2) * 64;
    const int wn = (wid & 3) * 32;

    const bool two = (mode == 0) || (mode == 2 && bn >= 1280);   // uniform per CTA

    const int srow = tid >> 1, shalf = tid & 1;
    const size_t gaBase = (size_t)(bm + srow) * K + shalf * 16;
    const size_t gbBase = (size_t)(bn + srow) * K + shalf * 16;
    const unsigned soff = srow * 80 + shalf * 32;

    const unsigned aBase = (unsigned)((wm + (lane & 7) + ((lane >> 3) & 1) * 8) * 80
                                      + ((lane >> 4) & 1) * 16);
    const unsigned bBase = (unsigned)((wn + (lane & 7)) * 80 + ((lane >> 3) & 1) * 16);

    float c[4][4][4] = {};
    const int NCH = K / 32;

    // prologue: stage chunk 0 into stage 0
    {
        unsigned base = sb + soff;
        cpa16(base,                Agh + gaBase);
        cpa16(base + 16,           Agh + gaBase + 8);
        if (two) {
            cpa16(base + GTB,      Agl + gaBase);
            cpa16(base + GTB + 16, Agl + gaBase + 8);
        }
        cpa16(base + 2 * GTB,      Bgh + gbBase);
        cpa16(base + 2 * GTB + 16, Bgh + gbBase + 8);
        CP_COMMIT();
    }

    for (int ch = 0; ch < NCH; ch++) {
        const int s = ch & 1;
        if (ch + 1 < NCH) {
            unsigned base = sb + (s ^ 1) * 3 * GTB + soff;
            size_t ka = gaBase + (size_t)(ch + 1) * 32;
            size_t kb = gbBase + (size_t)(ch + 1) * 32;
            cpa16(base,                Agh + ka);
            cpa16(base + 16,           Agh + ka + 8);
            if (two) {
                cpa16(base + GTB,      Agl + ka);
                cpa16(base + GTB + 16, Agl + ka + 8);
            }
            cpa16(base + 2 * GTB,      Bgh + kb);
            cpa16(base + 2 * GTB + 16, Bgh + kb + 8);
            CP_COMMIT();
            CP_WAIT1();
        } else {
            CP_WAIT0();
        }
        __syncthreads();

        const unsigned uAh = sb + s * 3 * GTB;
        const unsigned uAl = uAh + GTB;
        const unsigned uBh = uAh + 2 * GTB;

        #pragma unroll
        for (int ks = 0; ks < 2; ks++) {
            const unsigned ko = ks * 32;
            unsigned ah[4][4], bh[4][2];
            #pragma unroll
            for (int mi = 0; mi < 4; mi++)
                ldm_x4(ah[mi], uAh + aBase + mi * 16 * 80 + ko);
            #pragma unroll
            for (int ni = 0; ni < 4; ni++)
                ldm_x2(bh[ni][0], bh[ni][1], uBh + bBase + ni * 8 * 80 + ko);
            #pragma unroll
            for (int mi = 0; mi < 4; mi++)
                #pragma unroll
                for (int ni = 0; ni < 4; ni++)
                    mma16816h(c[mi][ni], ah[mi], bh[ni][0], bh[ni][1]);
            if (two) {
                unsigned al[4][4];
                #pragma unroll
                for (int mi = 0; mi < 4; mi++)
                    ldm_x4(al[mi], uAl + aBase + mi * 16 * 80 + ko);
                #pragma unroll
                for (int mi = 0; mi < 4; mi++)
                    #pragma unroll
                    for (int ni = 0; ni < 4; ni++)
                        mma16816h(c[mi][ni], al[mi], bh[ni][0], bh[ni][1]);
            }
        }
        __syncthreads();
    }

    // ---- epilogue ----
    if (mode != 2) {
        #pragma unroll
        for (int mi = 0; mi < 4; mi++)
            #pragma unroll
            for (int ni = 0; ni < 4; ni++) {
                int r = bm + wm + mi * 16 + lr;
                int col = bn + wn + ni * 8 + lc * 2;
                *(float2*)&C[(size_t)r * N + col] = make_float2(c[mi][ni][0], c[mi][ni][1]);
                *(float2*)&C[(size_t)(r + 8) * N + col] = make_float2(c[mi][ni][2], c[mi][ni][3]);
            }
    } else {
        if (bn < 1024) {
            #pragma unroll
            for (int mi = 0; mi < 4; mi++)
                #pragma unroll
                for (int ni = 0; ni < 4; ni++) {
                    int r = bm + wm + mi * 16 + lr;
                    int col = bn + wn + ni * 8 + lc * 2;
                    *(float2*)&C[(size_t)r * D + col] = make_float2(c[mi][ni][0], c[mi][ni][1]);
                    *(float2*)&C[(size_t)(r + 8) * D + col] = make_float2(c[mi][ni][2], c[mi][ni][3]);
                }
        } else if (bn < 1280) {
            #pragma unroll
            for (int mi = 0; mi < 4; mi++)
                #pragma unroll
                for (int ni = 0; ni < 4; ni++) {
                    int r = bm + wm + mi * 16 + lr;
                    int col = (bn - 1024) + wn + ni * 8 + lc * 2;
                    *(float2*)&C2[(size_t)r * KVD + col] = make_float2(c[mi][ni][0], c[mi][ni][1]);
                    *(float2*)&C2[(size_t)(r + 8) * KVD + col] = make_float2(c[mi][ni][2], c[mi][ni][3]);
                }
        } else {
            unsigned* V32 = (unsigned*)Cv;
            #pragma unroll
            for (int mi = 0; mi < 4; mi++)
                #pragma unroll
                for (int ni = 0; ni < 4; ni++) {
                    int r = bm + wm + mi * 16 + lr;
                    int col = (bn - 1280) + wn + ni * 8 + lc * 2;
                    V32[((size_t)r * KVD + col) >> 1] =
                        pack_fp16(__float2half_rn(c[mi][ni][0]), __float2half_rn(c[mi][ni][1]));
                    V32[((size_t)(r + 8) * KVD + col) >> 1] =
                        pack_fp16(__float2half_rn(c[mi][ni][2]), __float2half_rn(c[mi][ni][3]));
                }
        }
    }
}

// ---------------------------------------------------------------------------
// RMSNorm + RoPE: fp32 Q/K in, single fp16 out
// ---------------------------------------------------------------------------
__global__ void __launch_bounds__(256)
rmsrope_kernel(const float* __restrict__ Qf, const float* __restrict__ Kf,
               fp16* __restrict__ Qo, fp16* __restrict__ Ko,
               const float* __restrict__ rope_cos, const float* __restrict__ rope_sin,
               const float* __restrict__ q_scale, const float* __restrict__ k_scale) {
    const int w = blockIdx.x * 8 + (threadIdx.x >> 5);
    const int lane = threadIdx.x & 31;

    const float* p;
    fp16* op;
    const float* scale;
    int s_idx;
    if (w < 262144) {
        int ns = w >> 4;
        int h = w & 15;
        size_t base = (size_t)ns * D + h * HD;
        p = Qf + base; op = Qo + base;
        scale = q_scale;
        s_idx = ns & 255;
    } else {
        int w2 = w - 262144;
        int ns = w2 >> 2;
        int h = w2 & 3;
        size_t base = (size_t)ns * KVD + h * HD;
        p = Kf + base; op = Ko + base;
        scale = k_scale;
        s_idx = ns & 255;
    }

    float v1 = p[lane];
    float v2 = p[lane + 32];
    float ss = v1 * v1 + v2 * v2;
    #pragma unroll
    for (int o = 16; o; o >>= 1) ss += __shfl_xor_sync(0xffffffffu, ss, o);
    float r = rsqrtf(ss * (1.0f / 64.0f) + 1e-6f);

    float a = v1 * r * scale[lane];
    float b = v2 * r * scale[lane + 32];
    float cc = rope_cos[s_idx * 32 + lane];
    float sn = rope_sin[s_idx * 32 + lane];
    op[lane]      = __float2half_rn(a * cc - b * sn);
    op[lane + 32] = __float2half_rn(b * cc + a * sn);
}

// ---------------------------------------------------------------------------
// Flash-attention fp16: QK^T 1-pass (Q frags hoisted), PV 2-pass.
// Writes single fp16 O.
// ---------------------------------------------------------------------------
#define KVP 72
#define ATTN_SMEM (2 * 256 * KVP * 2)     // 73728 bytes

__global__ void __launch_bounds__(256, 1)
attn_mma(const fp16* __restrict__ Qg, const fp16* __restrict__ Kg,
         const fp16* __restrict__ Vg, fp16* __restrict__ Og) {
    extern __shared__ char sma[];
    fp16* sK = (fp16*)sma;
    fp16* sV = sK + 256 * KVP;

    const int bid = blockIdx.x;
    const int n = bid >> 4;
    const int h = bid & 15;
    const int hkv = h >> 2;
    const int tid = threadIdx.x;
    const int w = tid >> 5;
    const int lane = tid & 31;
    const int lr = lane >> 2, lc = lane & 3;

    // ---- stage K/V (single fp16, coalesced uint4) ----
    {
        const fp16* srcs[2] = {Kg, Vg};
        fp16* dsts[2] = {sK, sV};
        #pragma unroll
        for (int a = 0; a < 2; a++) {
            const char* src = (const char*)(srcs[a] + (size_t)n * 256 * KVD + hkv * HD);
            char* dst = (char*)dsts[a];
            for (int it = tid; it < 2048; it += 256) {
                int row = it >> 3, q = it & 7;
                *(uint4*)(dst + row * (KVP * 2) + q * 16) =
                    *(const uint4*)(src + (size_t)row * (KVD * 2) + q * 16);
            }
        }
    }
    __syncthreads();

    const unsigned uK = smem_u32(sK), uV = smem_u32(sV);
    const unsigned* Q32 = (const unsigned*)Qg;

    const int wq0 = w * 32;

    // ---- hoisted Q fragments (j-invariant) ----
    unsigned qf[4][2][4];
    #pragma unroll
    for (int kt = 0; kt < 4; kt++)
        #pragma unroll
        for (int mt = 0; mt < 2; mt++) {
            size_t row = (size_t)n * 256 + wq0 + mt * 16 + lr;
            size_t b0 = row * 512 + h * 32 + kt * 8 + lc;
            qf[kt][mt][0] = Q32[b0];
            qf[kt][mt][1] = Q32[b0 + 8 * 512];
            qf[kt][mt][2] = Q32[b0 + 4];
            qf[kt][mt][3] = Q32[b0 + 8 * 512 + 4];
        }

    float o[2][8][4] = {};
    float mrun[2][2] = {{-3e38f, -3e38f}, {-3e38f, -3e38f}};
    float lrun[2][2] = {{0.f, 0.f}, {0.f, 0.f}};

    for (int j = 0; j < 4; j++) {
        float c[2][8][4] = {};

        // ===== QK^T (single fp16 pass) =====
        #pragma unroll
        for (int kt = 0; kt < 4; kt++) {
            #pragma unroll
            for (int nt = 0; nt < 8; nt++) {
                int krow = j * 64 + nt * 8 + (lane & 7);
                int kcol = kt * 16 + ((lane >> 3) & 1) * 8;
                unsigned adr = (unsigned)(krow * KVP + kcol) * 2;
                unsigned k0, k1;
                ldm_x2(k0, k1, uK + adr);
                #pragma unroll
                for (int mt = 0; mt < 2; mt++)
                    mma16816h(c[mt][nt], qf[kt][mt], k0, k1);
            }
        }

        // ===== cap + mask + online softmax =====
        #pragma unroll
        for (int mt = 0; mt < 2; mt++) {
            #pragma unroll
            for (int half = 0; half < 2; half++) {
                const int qr = wq0 + mt * 16 + lr + 8 * half;
                float bmax = -3e38f;
                #pragma unroll
                for (int nt = 0; nt < 8; nt++) {
                    #pragma unroll
                    for (int e = 0; e < 2; e++) {
                        float s = c[mt][nt][2 * half + e] * 0.125f;
                        float t = __expf(s * 0.04f);
                        s = 50.0f * __fdividef(t - 1.0f, t + 1.0f);
                        int col = j * 64 + nt * 8 + 2 * lc + e;
                        if (!((qr >= NIMG) || (col < NIMG))) s = -3e38f;
                        c[mt][nt][2 * half + e] = s;
                        bmax = fmaxf(bmax, s);
                    }
                }
                bmax = fmaxf(bmax, __shfl_xor_sync(0xffffffffu, bmax, 1));
                bmax = fmaxf(bmax, __shfl_xor_sync(0xffffffffu, bmax, 2));
                float mold = mrun[mt][half];
                float mnew = fmaxf(mold, bmax);
                float resc = __expf(mold - mnew);
                float rs = 0.0f;
                #pragma unroll
                for (int nt = 0; nt < 8; nt++) {
                    #pragma unroll
                    for (int e = 0; e < 2; e++) {
                        float p = __expf(c[mt][nt][2 * half + e] - mnew);
                        c[mt][nt][2 * half + e] = p;
                        rs += p;
                    }
                }
                rs += __shfl_xor_sync(0xffffffffu, rs, 1);
                rs += __shfl_xor_sync(0xffffffffu, rs, 2);
                lrun[mt][half] = lrun[mt][half] * resc + rs;
                mrun[mt][half] = mnew;
                #pragma unroll
                for (int dt = 0; dt < 8; dt++) {
                    o[mt][dt][2 * half]     *= resc;
                    o[mt][dt][2 * half + 1] *= resc;
                }
            }
        }

        // ===== PV (P split fp16 h/l, V single fp16) =====
        #pragma unroll
        for (int kt = 0; kt < 4; kt++) {
            unsigned ph[2][4], pl[2][4];
            #pragma unroll
            for (int mt = 0; mt < 2; mt++) {
                fp16 h0, l0, h1, l1;
                split_fp16(c[mt][2 * kt][0], h0, l0);
                split_fp16(c[mt][2 * kt][1], h1, l1);
                ph[mt][0] = pack_fp16(h0, h1); pl[mt][0] = pack_fp16(l0, l1);
                split_fp16(c[mt][2 * kt][2], h0, l0);
                split_fp16(c[mt][2 * kt][3], h1, l1);
                ph[mt][1] = pack_fp16(h0, h1); pl[mt][1] = pack_fp16(l0, l1);
                split_fp16(c[mt][2 * kt + 1][0], h0, l0);
                split_fp16(c[mt][2 * kt + 1][1], h1, l1);
                ph[mt][2] = pack_fp16(h0, h1); pl[mt][2] = pack_fp16(l0, l1);
                split_fp16(c[mt][2 * kt + 1][2], h0, l0);
                split_fp16(c[mt][2 * kt + 1][3], h1, l1);
                ph[mt][3] = pack_fp16(h0, h1); pl[mt][3] = pack_fp16(l0, l1);
            }
            #pragma unroll
            for (int dt = 0; dt < 8; dt++) {
                int vrow = j * 64 + kt * 16 + (lane & 15);
                unsigned adr = (unsigned)(vrow * KVP + dt * 8) * 2;
                unsigned v0, v1;
                ldm_x2t(v0, v1, uV + adr);
                #pragma unroll
                for (int mt = 0; mt < 2; mt++) {
                    mma16816h(o[mt][dt], ph[mt], v0, v1);
                    mma16816h(o[mt][dt], pl[mt], v0, v1);
                }
            }
        }
    }

    // ===== epilogue: normalize + single fp16 store =====
    unsigned* O32 = (unsigned*)Og;
    #pragma unroll
    for (int mt = 0; mt < 2; mt++) {
        float inv0 = __fdividef(1.0f, lrun[mt][0]);
        float inv1 = __fdividef(1.0f, lrun[mt][1]);
        size_t r0 = (size_t)n * 256 + wq0 + mt * 16 + lr;
        #pragma unroll
        for (int dt = 0; dt < 8; dt++) {
            size_t i0 = r0 * 512 + h * 32 + dt * 4 + lc;
            O32[i0] = pack_fp16(__float2half_rn(o[mt][dt][0] * inv0),
                                __float2half_rn(o[mt][dt][1] * inv0));
            size_t i1 = (r0 + 8) * 512 + h * 32 + dt * 4 + lc;
            O32[i1] = pack_fp16(__float2half_rn(o[mt][dt][2] * inv1),
                                __float2half_rn(o[mt][dt][3] * inv1));
        }
    }
}

// ---------------------------------------------------------------------------
extern "C" void kernel_launch(void* const* d_in, const int* in_sizes, int n_in,
                              void* d_out, int out_size) {
    const float* x        = (const float*)d_in[0];
    const float* rope_cos = (const float*)d_in[2];
    const float* rope_sin = (const float*)d_in[3];
    const float* Wq       = (const float*)d_in[4];
    const float* Wk       = (const float*)d_in[5];
    const float* Wv       = (const float*)d_in[6];
    const float* Wo       = (const float*)d_in[7];
    const float* q_scale  = (const float*)d_in[8];
    const float* k_scale  = (const float*)d_in[9];
    float* out = (float*)d_out;

    char* base;
    cudaGetSymbolAddress((void**)&base, g_arena);
    size_t cur = 0;
    auto alloc = [&](size_t bytes) { char* p = base + cur; cur += (bytes + 255) & ~255ULL; return p; };

    float* Qf  = (float*)alloc((size_t)MROWS * D * 4);
    float* Kf  = (float*)alloc((size_t)MROWS * KVD * 4);
    fp16* xh   = (fp16*)alloc((size_t)MROWS * D * 2);
    fp16* xl   = (fp16*)alloc((size_t)MROWS * D * 2);
    fp16* Q16  = (fp16*)alloc((size_t)MROWS * D * 2);
    fp16* K16  = (fp16*)alloc((size_t)MROWS * KVD * 2);
    fp16* V16  = (fp16*)alloc((size_t)MROWS * KVD * 2);
    fp16* O16  = (fp16*)alloc((size_t)MROWS * D * 2);
    fp16* WTh  = (fp16*)alloc((size_t)NFUSE * D * 2);
    fp16* WoTh = (fp16*)alloc((size_t)D * D * 2);

    cudaFuncSetAttribute(gemm_fp16, cudaFuncAttributeMaxDynamicSharedMemorySize, GEMM_SMEM);
    cudaFuncSetAttribute(attn_mma, cudaFuncAttributeMaxDynamicSharedMemorySize, ATTN_SMEM);

    dim3 thr(256);
    // prepasses
    split_x_fp16<<<MROWS * D / 4 / 256, 256>>>(x, xh, xl, MROWS * D / 4);
    transp_half<<<dim3(D / 32, D / 32), dim3(32, 8)>>>(Wq, WTh, D, D, 0);
    transp_half<<<dim3(KVD / 32, D / 32), dim3(32, 8)>>>(Wk, WTh, D, KVD, 1024);
    transp_half<<<dim3(KVD / 32, D / 32), dim3(32, 8)>>>(Wv, WTh, D, KVD, 1280);
    transp_half<<<dim3(D / 32, D / 32), dim3(32, 8)>>>(Wo, WoTh, D, D, 0);

    // fused QKV projection (Q,K 1-pass; V 2-pass -> fp16)
    gemm_fp16<<<dim3(NFUSE / 128, MROWS / 128), thr, GEMM_SMEM>>>(
        xh, xl, WTh, Qf, Kf, V16, MROWS, NFUSE, D, 2);

    // rmsnorm + rope -> single fp16
    rmsrope_kernel<<<(262144 + 65536) / 8, thr>>>(
        Qf, Kf, Q16, K16, rope_cos, rope_sin, q_scale, k_scale);

    // attention (fp16: QK 1-pass, PV 2-pass) -> O single fp16
    attn_mma<<<NB * NH, thr, ATTN_SMEM>>>(Q16, K16, V16, O16);

    // output projection (fp16 1-pass: O-side fp16 rounding is within budget)
    gemm_fp16<<<dim3(D / 128, MROWS / 128), thr, GEMM_SMEM>>>(
        O16, nullptr, WoTh, out, nullptr, nullptr, MROWS, D, D, 1);
}

// round 16
// speedup vs baseline: 4.0871x; 1.0159x over previous
#include <cuda_runtime.h>
#include <cuda_bf16.h>
#include <cuda_fp16.h>
#include <math.h>

#define NB 64
#define S 256
#define D 1024
#define NH 16
#define NKV 4
#define HD 64
#define NIMG 240
#define MROWS (NB * S)       // 16384
#define KVD (NKV * HD)       // 256
#define NFUSE 1536           // packed QKV output columns

typedef __half fp16;

#define ARENA_BYTES 420000000ULL
__device__ __align__(256) char g_arena[ARENA_BYTES];

// ---------------------------------------------------------------------------
// helpers
// ---------------------------------------------------------------------------
__device__ __forceinline__ unsigned smem_u32(const void* p) {
    unsigned a;
    asm("{ .reg .u64 t; cvta.to.shared.u64 t, %1; cvt.u32.u64 %0, t; }" : "=r"(a) : "l"(p));
    return a;
}
__device__ __forceinline__ void cpa16(unsigned saddr, const void* g) {
    asm volatile("cp.async.cg.shared.global [%0], [%1], 16;" :: "r"(saddr), "l"(g));
}
#define CP_COMMIT() asm volatile("cp.async.commit_group;")
#define CP_WAIT1()  asm volatile("cp.async.wait_group 1;")
#define CP_WAIT0()  asm volatile("cp.async.wait_group 0;")

__device__ __forceinline__ unsigned pack_fp16(fp16 a, fp16 b) {
    return (unsigned)__half_as_ushort(a) | ((unsigned)__half_as_ushort(b) << 16);
}
__device__ __forceinline__ void split_fp16(float x, fp16& h, fp16& l) {
    h = __float2half_rn(x);
    l = __float2half_rn(x - __half2float(h));
}
__device__ __forceinline__ void mma16816h(float c[4], const unsigned a[4],
                                          unsigned b0, unsigned b1) {
    asm volatile(
        "mma.sync.aligned.m16n8k16.row.col.f32.f16.f16.f32 "
        "{%0,%1,%2,%3}, {%4,%5,%6,%7}, {%8,%9}, {%0,%1,%2,%3};"
        : "+f"(c[0]), "+f"(c[1]), "+f"(c[2]), "+f"(c[3])
        : "r"(a[0]), "r"(a[1]), "r"(a[2]), "r"(a[3]), "r"(b0), "r"(b1));
}
__device__ __forceinline__ void ldm_x4(unsigned r[4], unsigned addr) {
    asm volatile("ldmatrix.sync.aligned.m8n8.x4.shared.b16 {%0,%1,%2,%3}, [%4];"
                 : "=r"(r[0]), "=r"(r[1]), "=r"(r[2]), "=r"(r[3]) : "r"(addr));
}
__device__ __forceinline__ void ldm_x2(unsigned& r0, unsigned& r1, unsigned addr) {
    asm volatile("ldmatrix.sync.aligned.m8n8.x2.shared.b16 {%0,%1}, [%2];"
                 : "=r"(r0), "=r"(r1) : "r"(addr));
}
__device__ __forceinline__ void ldm_x2t(unsigned& r0, unsigned& r1, unsigned addr) {
    asm volatile("ldmatrix.sync.aligned.m8n8.x2.trans.shared.b16 {%0,%1}, [%2];"
                 : "=r"(r0), "=r"(r1) : "r"(addr));
}

// ---------------------------------------------------------------------------
// Prepass: fp32 -> fp16 (x)
// ---------------------------------------------------------------------------
__global__ void __launch_bounds__(256)
cvt_fp16(const float* __restrict__ x, fp16* __restrict__ xh, int total4) {
    int i4 = blockIdx.x * 256 + threadIdx.x;
    if (i4 >= total4) return;
    int i = i4 * 4;
    float4 v = *(const float4*)(x + i);
    *(uint2*)(xh + i) = make_uint2(
        pack_fp16(__float2half_rn(v.x), __float2half_rn(v.y)),
        pack_fp16(__float2half_rn(v.z), __float2half_rn(v.w)));
}

// ---------------------------------------------------------------------------
// Prepass: weight transpose + fp16 convert: W[k][n] -> T[rowOff + n][k]
// ---------------------------------------------------------------------------
__global__ void __launch_bounds__(256)
transp_half(const float* __restrict__ W, fp16* __restrict__ T,
            int Kd, int Nd, int rowOff) {
    __shared__ float t[32][33];
    const int n0 = blockIdx.x * 32, k0 = blockIdx.y * 32;
    const int tx = threadIdx.x, ty = threadIdx.y;   // 32 x 8
    #pragma unroll
    for (int i = 0; i < 4; i++)
        t[ty + 8 * i][tx] = W[(size_t)(k0 + ty + 8 * i) * Nd + n0 + tx];
    __syncthreads();
    #pragma unroll
    for (int i = 0; i < 4; i++)
        T[(size_t)(rowOff + n0 + ty + 8 * i) * Kd + k0 + tx] =
            __float2half_rn(t[tx][ty + 8 * i]);
}

// ---------------------------------------------------------------------------
// fp16 1-pass GEMM: C = A @ B^T, A fp16 [M][K], B fp16 [N][K].
// CTA 128x128, BK=32, cp.async double buffer, 8 warps (2x4), warp 64x32.
// mode 0: C fp32 stride N (Wo -> out).
// mode 2: fused QKV routing, all fp16 stores:
//         cols<1024 -> Cq stride D; <1280 -> Ck stride KVD; else Cv stride KVD.
// ---------------------------------------------------------------------------
#define GTB (128 * 80)              // tile bytes: 128 rows x 80B pitch (64B data)
#define GEMM_SMEM (2 * 2 * GTB)     // 40960

__global__ void __launch_bounds__(256)
gemm_fp16(const fp16* __restrict__ Ag, const fp16* __restrict__ Bg,
          float* __restrict__ C,
          fp16* __restrict__ Cq, fp16* __restrict__ Ck, fp16* __restrict__ Cv,
          int M, int N, int K, int mode) {
    extern __shared__ char smg[];
    const unsigned sb = smem_u32(smg);
    const int tid = threadIdx.x;
    const int wid = tid >> 5;
    const int lane = tid & 31;
    const int lr = lane >> 2, lc = lane & 3;

    const int bm = blockIdx.y * 128;
    const int bn = blockIdx.x * 128;
    const int wm = (wid >> 2) * 64;
    const int wn = (wid & 3) * 32;

    const int srow = tid >> 1, shalf = tid & 1;
    const size_t gaBase = (size_t)(bm + srow) * K + shalf * 16;
    const size_t gbBase = (size_t)(bn + srow) * K + shalf * 16;
    const unsigned soff = srow * 80 + shalf * 32;

    const unsigned aBase = (unsigned)((wm + (lane & 7) + ((lane >> 3) & 1) * 8) * 80
                                      + ((lane >> 4) & 1) * 16);
    const unsigned bBase = (unsigned)((wn + (lane & 7)) * 80 + ((lane >> 3) & 1) * 16);

    float c[4][4][4] = {};
    const int NCH = K / 32;

    // prologue: stage chunk 0 into stage 0
    {
        unsigned base = sb + soff;
        cpa16(base,            Ag + gaBase);
        cpa16(base + 16,       Ag + gaBase + 8);
        cpa16(base + GTB,      Bg + gbBase);
        cpa16(base + GTB + 16, Bg + gbBase + 8);
        CP_COMMIT();
    }

    for (int ch = 0; ch < NCH; ch++) {
        const int s = ch & 1;
        if (ch + 1 < NCH) {
            unsigned base = sb + (s ^ 1) * 2 * GTB + soff;
            size_t ka = gaBase + (size_t)(ch + 1) * 32;
            size_t kb = gbBase + (size_t)(ch + 1) * 32;
            cpa16(base,            Ag + ka);
            cpa16(base + 16,       Ag + ka + 8);
            cpa16(base + GTB,      Bg + kb);
            cpa16(base + GTB + 16, Bg + kb + 8);
            CP_COMMIT();
            CP_WAIT1();
        } else {
            CP_WAIT0();
        }
        __syncthreads();

        const unsigned uA = sb + s * 2 * GTB;
        const unsigned uB = uA + GTB;

        #pragma unroll
        for (int ks = 0; ks < 2; ks++) {
            const unsigned ko = ks * 32;
            unsigned ah[4][4], bh[4][2];
            #pragma unroll
            for (int mi = 0; mi < 4; mi++)
                ldm_x4(ah[mi], uA + aBase + mi * 16 * 80 + ko);
            #pragma unroll
            for (int ni = 0; ni < 4; ni++)
                ldm_x2(bh[ni][0], bh[ni][1], uB + bBase + ni * 8 * 80 + ko);
            #pragma unroll
            for (int mi = 0; mi < 4; mi++)
                #pragma unroll
                for (int ni = 0; ni < 4; ni++)
                    mma16816h(c[mi][ni], ah[mi], bh[ni][0], bh[ni][1]);
        }
        __syncthreads();
    }

    // ---- epilogue ----
    if (mode == 0) {
        #pragma unroll
        for (int mi = 0; mi < 4; mi++)
            #pragma unroll
            for (int ni = 0; ni < 4; ni++) {
                int r = bm + wm + mi * 16 + lr;
                int col = bn + wn + ni * 8 + lc * 2;
                *(float2*)&C[(size_t)r * N + col] = make_float2(c[mi][ni][0], c[mi][ni][1]);
                *(float2*)&C[(size_t)(r + 8) * N + col] = make_float2(c[mi][ni][2], c[mi][ni][3]);
            }
    } else {
        // fp16 routed stores (bn uniform per CTA)
        unsigned* dst;
        int stride, colOff;
        if (bn < 1024)      { dst = (unsigned*)Cq; stride = D;   colOff = 0; }
        else if (bn < 1280) { dst = (unsigned*)Ck; stride = KVD; colOff = 1024; }
        else                { dst = (unsigned*)Cv; stride = KVD; colOff = 1280; }
        #pragma unroll
        for (int mi = 0; mi < 4; mi++)
            #pragma unroll
            for (int ni = 0; ni < 4; ni++) {
                int r = bm + wm + mi * 16 + lr;
                int col = (bn - colOff) + wn + ni * 8 + lc * 2;
                dst[((size_t)r * stride + col) >> 1] =
                    pack_fp16(__float2half_rn(c[mi][ni][0]), __float2half_rn(c[mi][ni][1]));
                dst[((size_t)(r + 8) * stride + col) >> 1] =
                    pack_fp16(__float2half_rn(c[mi][ni][2]), __float2half_rn(c[mi][ni][3]));
            }
    }
}

// ---------------------------------------------------------------------------
// RMSNorm + RoPE: fp16 Q/K in, fp16 out (score path is softmax-damped)
// ---------------------------------------------------------------------------
__global__ void __launch_bounds__(256)
rmsrope_kernel(const fp16* __restrict__ Qr, const fp16* __restrict__ Kr,
               fp16* __restrict__ Qo, fp16* __restrict__ Ko,
               const float* __restrict__ rope_cos, const float* __restrict__ rope_sin,
               const float* __restrict__ q_scale, const float* __restrict__ k_scale) {
    const int w = blockIdx.x * 8 + (threadIdx.x >> 5);
    const int lane = threadIdx.x & 31;

    const fp16* p;
    fp16* op;
    const float* scale;
    int s_idx;
    if (w < 262144) {
        int ns = w >> 4;
        int h = w & 15;
        size_t base = (size_t)ns * D + h * HD;
        p = Qr + base; op = Qo + base;
        scale = q_scale;
        s_idx = ns & 255;
    } else {
        int w2 = w - 262144;
        int ns = w2 >> 2;
        int h = w2 & 3;
        size_t base = (size_t)ns * KVD + h * HD;
        p = Kr + base; op = Ko + base;
        scale = k_scale;
        s_idx = ns & 255;
    }

    float v1 = __half2float(p[lane]);
    float v2 = __half2float(p[lane + 32]);
    float ss = v1 * v1 + v2 * v2;
    #pragma unroll
    for (int o = 16; o; o >>= 1) ss += __shfl_xor_sync(0xffffffffu, ss, o);
    float r = rsqrtf(ss * (1.0f / 64.0f) + 1e-6f);

    float a = v1 * r * scale[lane];
    float b = v2 * r * scale[lane + 32];
    float cc = rope_cos[s_idx * 32 + lane];
    float sn = rope_sin[s_idx * 32 + lane];
    op[lane]      = __float2half_rn(a * cc - b * sn);
    op[lane + 32] = __float2half_rn(b * cc + a * sn);
}

// ---------------------------------------------------------------------------
// Flash-attention fp16: QK^T 1-pass (Q frags hoisted), PV 2-pass.
// Writes single fp16 O.
// ---------------------------------------------------------------------------
#define KVP 72
#define ATTN_SMEM (2 * 256 * KVP * 2)     // 73728 bytes

__global__ void __launch_bounds__(256, 1)
attn_mma(const fp16* __restrict__ Qg, const fp16* __restrict__ Kg,
         const fp16* __restrict__ Vg, fp16* __restrict__ Og) {
    extern __shared__ char sma[];
    fp16* sK = (fp16*)sma;
    fp16* sV = sK + 256 * KVP;

    const int bid = blockIdx.x;
    const int n = bid >> 4;
    const int h = bid & 15;
    const int hkv = h >> 2;
    const int tid = threadIdx.x;
    const int w = tid >> 5;
    const int lane = tid & 31;
    const int lr = lane >> 2, lc = lane & 3;

    // ---- stage K/V (single fp16, coalesced uint4) ----
    {
        const fp16* srcs[2] = {Kg, Vg};
        fp16* dsts[2] = {sK, sV};
        #pragma unroll
        for (int a = 0; a < 2; a++) {
            const char* src = (const char*)(srcs[a] + (size_t)n * 256 * KVD + hkv * HD);
            char* dst = (char*)dsts[a];
            for (int it = tid; it < 2048; it += 256) {
                int row = it >> 3, q = it & 7;
                *(uint4*)(dst + row * (KVP * 2) + q * 16) =
                    *(const uint4*)(src + (size_t)row * (KVD * 2) + q * 16);
            }
        }
    }
    __syncthreads();

    const unsigned uK = smem_u32(sK), uV = smem_u32(sV);
    const unsigned* Q32 = (const unsigned*)Qg;

    const int wq0 = w * 32;

    // ---- hoisted Q fragments (j-invariant) ----
    unsigned qf[4][2][4];
    #pragma unroll
    for (int kt = 0; kt < 4; kt++)
        #pragma unroll
        for (int mt = 0; mt < 2; mt++) {
            size_t row = (size_t)n * 256 + wq0 + mt * 16 + lr;
            size_t b0 = row * 512 + h * 32 + kt * 8 + lc;
            qf[kt][mt][0] = Q32[b0];
            qf[kt][mt][1] = Q32[b0 + 8 * 512];
            qf[kt][mt][2] = Q32[b0 + 4];
            qf[kt][mt][3] = Q32[b0 + 8 * 512 + 4];
        }

    float o[2][8][4] = {};
    float mrun[2][2] = {{-3e38f, -3e38f}, {-3e38f, -3e38f}};
    float lrun[2][2] = {{0.f, 0.f}, {0.f, 0.f}};

    for (int j = 0; j < 4; j++) {
        float c[2][8][4] = {};

        // ===== QK^T (single fp16 pass) =====
        #pragma unroll
        for (int kt = 0; kt < 4; kt++) {
            #pragma unroll
            for (int nt = 0; nt < 8; nt++) {
                int krow = j * 64 + nt * 8 + (lane & 7);
                int kcol = kt * 16 + ((lane >> 3) & 1) * 8;
                unsigned adr = (unsigned)(krow * KVP + kcol) * 2;
                unsigned k0, k1;
                ldm_x2(k0, k1, uK + adr);
                #pragma unroll
                for (int mt = 0; mt < 2; mt++)
                    mma16816h(c[mt][nt], qf[kt][mt], k0, k1);
            }
        }

        // ===== cap + mask + online softmax =====
        #pragma unroll
        for (int mt = 0; mt < 2; mt++) {
            #pragma unroll
            for (int half = 0; half < 2; half++) {
                const int qr = wq0 + mt * 16 + lr + 8 * half;
                float bmax = -3e38f;
                #pragma unroll
                for (int nt = 0; nt < 8; nt++) {
                    #pragma unroll
                    for (int e = 0; e < 2; e++) {
                        float s = c[mt][nt][2 * half + e] * 0.125f;
                        float t = __expf(s * 0.04f);
                        s = 50.0f * __fdividef(t - 1.0f, t + 1.0f);
                        int col = j * 64 + nt * 8 + 2 * lc + e;
                        if (!((qr >= NIMG) || (col < NIMG))) s = -3e38f;
                        c[mt][nt][2 * half + e] = s;
                        bmax = fmaxf(bmax, s);
                    }
                }
                bmax = fmaxf(bmax, __shfl_xor_sync(0xffffffffu, bmax, 1));
                bmax = fmaxf(bmax, __shfl_xor_sync(0xffffffffu, bmax, 2));
                float mold = mrun[mt][half];
                float mnew = fmaxf(mold, bmax);
                float resc = __expf(mold - mnew);
                float rs = 0.0f;
                #pragma unroll
                for (int nt = 0; nt < 8; nt++) {
                    #pragma unroll
                    for (int e = 0; e < 2; e++) {
                        float p = __expf(c[mt][nt][2 * half + e] - mnew);
                        c[mt][nt][2 * half + e] = p;
                        rs += p;
                    }
                }
                rs += __shfl_xor_sync(0xffffffffu, rs, 1);
                rs += __shfl_xor_sync(0xffffffffu, rs, 2);
                lrun[mt][half] = lrun[mt][half] * resc + rs;
                mrun[mt][half] = mnew;
                #pragma unroll
                for (int dt = 0; dt < 8; dt++) {
                    o[mt][dt][2 * half]     *= resc;
                    o[mt][dt][2 * half + 1] *= resc;
                }
            }
        }

        // ===== PV (P split fp16 h/l, V single fp16) =====
        #pragma unroll
        for (int kt = 0; kt < 4; kt++) {
            unsigned ph[2][4], pl[2][4];
            #pragma unroll
            for (int mt = 0; mt < 2; mt++) {
                fp16 h0, l0, h1, l1;
                split_fp16(c[mt][2 * kt][0], h0, l0);
                split_fp16(c[mt][2 * kt][1], h1, l1);
                ph[mt][0] = pack_fp16(h0, h1); pl[mt][0] = pack_fp16(l0, l1);
                split_fp16(c[mt][2 * kt][2], h0, l0);
                split_fp16(c[mt][2 * kt][3], h1, l1);
                ph[mt][1] = pack_fp16(h0, h1); pl[mt][1] = pack_fp16(l0, l1);
                split_fp16(c[mt][2 * kt + 1][0], h0, l0);
                split_fp16(c[mt][2 * kt + 1][1], h1, l1);
                ph[mt][2] = pack_fp16(h0, h1); pl[mt][2] = pack_fp16(l0, l1);
                split_fp16(c[mt][2 * kt + 1][2], h0, l0);
                split_fp16(c[mt][2 * kt + 1][3], h1, l1);
                ph[mt][3] = pack_fp16(h0, h1); pl[mt][3] = pack_fp16(l0, l1);
            }
            #pragma unroll
            for (int dt = 0; dt < 8; dt++) {
                int vrow = j * 64 + kt * 16 + (lane & 15);
                unsigned adr = (unsigned)(vrow * KVP + dt * 8) * 2;
                unsigned v0, v1;
                ldm_x2t(v0, v1, uV + adr);
                #pragma unroll
                for (int mt = 0; mt < 2; mt++) {
                    mma16816h(o[mt][dt], ph[mt], v0, v1);
                    mma16816h(o[mt][dt], pl[mt], v0, v1);
                }
            }
        }
    }

    // ===== epilogue: normalize + single fp16 store =====
    unsigned* O32 = (unsigned*)Og;
    #pragma unroll
    for (int mt = 0; mt < 2; mt++) {
        float inv0 = __fdividef(1.0f, lrun[mt][0]);
        float inv1 = __fdividef(1.0f, lrun[mt][1]);
        size_t r0 = (size_t)n * 256 + wq0 + mt * 16 + lr;
        #pragma unroll
        for (int dt = 0; dt < 8; dt++) {
            size_t i0 = r0 * 512 + h * 32 + dt * 4 + lc;
            O32[i0] = pack_fp16(__float2half_rn(o[mt][dt][0] * inv0),
                                __float2half_rn(o[mt][dt][1] * inv0));
            size_t i1 = (r0 + 8) * 512 + h * 32 + dt * 4 + lc;
            O32[i1] = pack_fp16(__float2half_rn(o[mt][dt][2] * inv1),
                                __float2half_rn(o[mt][dt][3] * inv1));
        }
    }
}

// ---------------------------------------------------------------------------
extern "C" void kernel_launch(void* const* d_in, const int* in_sizes, int n_in,
                              void* d_out, int out_size) {
    const float* x        = (const float*)d_in[0];
    const float* rope_cos = (const float*)d_in[2];
    const float* rope_sin = (const float*)d_in[3];
    const float* Wq       = (const float*)d_in[4];
    const float* Wk       = (const float*)d_in[5];
    const float* Wv       = (const float*)d_in[6];
    const float* Wo       = (const float*)d_in[7];
    const float* q_scale  = (const float*)d_in[8];
    const float* k_scale  = (const float*)d_in[9];
    float* out = (float*)d_out;

    char* base;
    cudaGetSymbolAddress((void**)&base, g_arena);
    size_t cur = 0;
    auto alloc = [&](size_t bytes) { char* p = base + cur; cur += (bytes + 255) & ~255ULL; return p; };

    fp16* xh    = (fp16*)alloc((size_t)MROWS * D * 2);
    fp16* Qraw  = (fp16*)alloc((size_t)MROWS * D * 2);
    fp16* Kraw  = (fp16*)alloc((size_t)MROWS * KVD * 2);
    fp16* V16   = (fp16*)alloc((size_t)MROWS * KVD * 2);
    fp16* Q16   = (fp16*)alloc((size_t)MROWS * D * 2);
    fp16* K16   = (fp16*)alloc((size_t)MROWS * KVD * 2);
    fp16* O16   = (fp16*)alloc((size_t)MROWS * D * 2);
    fp16* WTh   = (fp16*)alloc((size_t)NFUSE * D * 2);
    fp16* WoTh  = (fp16*)alloc((size_t)D * D * 2);

    cudaFuncSetAttribute(gemm_fp16, cudaFuncAttributeMaxDynamicSharedMemorySize, GEMM_SMEM);
    cudaFuncSetAttribute(attn_mma, cudaFuncAttributeMaxDynamicSharedMemorySize, ATTN_SMEM);

    dim3 thr(256);
    // prepasses
    cvt_fp16<<<MROWS * D / 4 / 256, 256>>>(x, xh, MROWS * D / 4);
    transp_half<<<dim3(D / 32, D / 32), dim3(32, 8)>>>(Wq, WTh, D, D, 0);
    transp_half<<<dim3(KVD / 32, D / 32), dim3(32, 8)>>>(Wk, WTh, D, KVD, 1024);
    transp_half<<<dim3(KVD / 32, D / 32), dim3(32, 8)>>>(Wv, WTh, D, KVD, 1280);
    transp_half<<<dim3(D / 32, D / 32), dim3(32, 8)>>>(Wo, WoTh, D, D, 0);

    // fused QKV projection (1-pass fp16; Q/K/V all written fp16)
    gemm_fp16<<<dim3(NFUSE / 128, MROWS / 128), thr, GEMM_SMEM>>>(
        xh, WTh, nullptr, Qraw, Kraw, V16, MROWS, NFUSE, D, 2);

    // rmsnorm + rope (fp16 in/out)
    rmsrope_kernel<<<(262144 + 65536) / 8, thr>>>(
        Qraw, Kraw, Q16, K16, rope_cos, rope_sin, q_scale, k_scale);

    // attention (fp16: QK 1-pass, PV 2-pass) -> O single fp16
    attn_mma<<<NB * NH, thr, ATTN_SMEM>>>(Q16, K16, V16, O16);

    // output projection (fp16 1-pass) -> fp32 out
    gemm_fp16<<<dim3(D / 128, MROWS / 128), thr, GEMM_SMEM>>>(
        O16, WoTh, out, nullptr, nullptr, nullptr, MROWS, D, D, 0);
}